// round 14
// baseline (speedup 1.0000x reference)
#include <cuda_runtime.h>
#include <cuda_bf16.h>
#include <cstdint>
#include <math.h>

// Problem dims: N=8, T=64, F=512, E=64
#define PITCH 65

// Arch-feature gate: tcgen05 exists only on sm_100a/sm_103a ('a' targets).
#if defined(__CUDA_ARCH__) && (defined(__CUDA_ARCH_FEAT_SM103_ALL) || \
    defined(__CUDA_ARCH_FEAT_SM100_ALL) || \
    (defined(__CUDA_ARCH_SPECIFIC__) && (__CUDA_ARCH_SPECIFIC__ >= 1000)))
#define ATTN_TCGEN 1
#else
#define ATTN_TCGEN 0
#endif

#define NELEM (8u * 64u * 512u * 64u)
// Projected Q/K in bf16 hi/lo, layout [n][e][f][t]
__device__ __nv_bfloat16 g_Qhi[NELEM];
__device__ __nv_bfloat16 g_Qlo[NELEM];
__device__ __nv_bfloat16 g_Khi[NELEM];
__device__ __nv_bfloat16 g_Klo[NELEM];
// V transposed, bf16 hi/lo, layout [n][e][t][f] (written directly by proj_tc)
__device__ __nv_bfloat16 g_Vthi[NELEM];
__device__ __nv_bfloat16 g_Vtlo[NELEM];
// Attention output fp32 [n][e][q][t]
__device__ float g_Op[NELEM];

// ============================================================================
// PTX helpers
// ============================================================================
__device__ __forceinline__ uint32_t smem_u32(const void* p) {
    uint32_t a;
    asm("{ .reg .u64 t; cvta.to.shared.u64 t, %1; cvt.u32.u64 %0, t; }"
        : "=r"(a) : "l"(p));
    return a;
}
#if ATTN_TCGEN
__device__ __forceinline__ uint32_t elect_one() {
    uint32_t p;
    asm volatile("{\n\t.reg .pred p;\n\telect.sync _|p, 0xFFFFFFFF;\n\t"
                 "selp.b32 %0, 1, 0, p;\n\t}" : "=r"(p));
    return p;
}
#endif
#define MBAR_INIT(a, c) \
    asm volatile("mbarrier.init.shared.b64 [%0], %1;" :: "r"(a), "r"(c) : "memory")
#define MBAR_WAIT(a, ph) do { \
    uint32_t _m = (a), _p = (ph), _d; \
    asm volatile("{\n\t.reg .pred p;\n\t" \
        "mbarrier.try_wait.parity.acquire.cta.shared::cta.b64 p, [%1], %2;\n\t" \
        "selp.b32 %0, 1, 0, p;\n\t}" : "=r"(_d) : "r"(_m), "r"(_p) : "memory"); \
    if (!_d) { \
        asm volatile("{\n\t.reg .pred P1;\n\tWL_%=: \n\t" \
            "mbarrier.try_wait.parity.acquire.cta.shared::cta.b64 P1, [%0], %1, 0x989680;\n\t" \
            "@P1 bra.uni WD_%=;\n\tbra.uni WL_%=;\n\tWD_%=: \n\t}" \
            :: "r"(_m), "r"(_p) : "memory"); \
    } } while (0)

#define TC_ALLOC(sa, n)  asm volatile( \
    "tcgen05.alloc.cta_group::1.sync.aligned.shared::cta.b32 [%0], %1;" \
    :: "r"(sa), "r"(n) : "memory")
#define TC_DEALLOC(t, n) asm volatile( \
    "tcgen05.dealloc.cta_group::1.sync.aligned.b32 %0, %1;" :: "r"(t), "r"(n))
#define TC_RELINQ() asm volatile("tcgen05.relinquish_alloc_permit.cta_group::1.sync.aligned;")
#define TC_COMMIT(mb) asm volatile( \
    "tcgen05.commit.cta_group::1.mbarrier::arrive::one.shared::cluster.b64 [%0];" \
    :: "r"(mb) : "memory")
#define TC_WAIT_LD() asm volatile("tcgen05.wait::ld.sync.aligned;" ::: "memory")
#define TC_FENCE_BEFORE() asm volatile("tcgen05.fence::before_thread_sync;" ::: "memory")
#define TC_FENCE_AFTER()  asm volatile("tcgen05.fence::after_thread_sync;" ::: "memory")
#define FENCE_ASYNC() asm volatile("fence.proxy.async.shared::cta;" ::: "memory")

#define TC_LD_X32(r, ta) asm volatile( \
    "tcgen05.ld.sync.aligned.32x32b.x32.b32 " \
    "{%0,%1,%2,%3,%4,%5,%6,%7,%8,%9,%10,%11,%12,%13,%14,%15," \
    "%16,%17,%18,%19,%20,%21,%22,%23,%24,%25,%26,%27,%28,%29,%30,%31}, [%32];" \
    : "=r"((r)[0]),"=r"((r)[1]),"=r"((r)[2]),"=r"((r)[3]), \
      "=r"((r)[4]),"=r"((r)[5]),"=r"((r)[6]),"=r"((r)[7]), \
      "=r"((r)[8]),"=r"((r)[9]),"=r"((r)[10]),"=r"((r)[11]), \
      "=r"((r)[12]),"=r"((r)[13]),"=r"((r)[14]),"=r"((r)[15]), \
      "=r"((r)[16]),"=r"((r)[17]),"=r"((r)[18]),"=r"((r)[19]), \
      "=r"((r)[20]),"=r"((r)[21]),"=r"((r)[22]),"=r"((r)[23]), \
      "=r"((r)[24]),"=r"((r)[25]),"=r"((r)[26]),"=r"((r)[27]), \
      "=r"((r)[28]),"=r"((r)[29]),"=r"((r)[30]),"=r"((r)[31]) \
    : "r"(ta))

#if ATTN_TCGEN
__device__ __forceinline__ void mma_bf16_ss(uint32_t d, uint64_t a, uint64_t b,
                                            uint32_t idesc, bool en) {
    uint32_t e = en ? 1u : 0u;
    asm volatile(
        "{\n\t.reg .pred p;\n\tsetp.ne.u32 p, %5, 0;\n\t"
        "tcgen05.mma.cta_group::1.kind::f16 [%0], %1, %2, %3, {%4,%4,%4,%4}, p;\n\t}"
        :: "r"(d), "l"(a), "l"(b), "r"(idesc), "r"(0u), "r"(e) : "memory");
}
#endif

// SMEM desc: SW128, version=1(Blackwell), SBO=64, LBO=1
static __device__ __forceinline__ uint64_t make_desc(uint32_t addr) {
    const uint64_t base = (uint64_t(2) << 61) | (uint64_t(1) << 46) |
                          (uint64_t(64) << 32) | (uint64_t(1) << 16);
    return base | ((uint64_t)(addr >> 4) & 0x3FFF);
}

// idesc kind::f16 bf16: dtype=F32(1<<4), atype=BF16(1<<7), btype=BF16(1<<10),
// N=64 ((64/8)<<17), M=128 ((128/16)<<24)
#define IDESC_BF16 ((1u<<4) | (1u<<7) | (1u<<10) | (8u<<17) | (8u<<24))

__device__ __forceinline__ uint32_t swz(uint32_t off) {
    return off ^ ((off >> 3) & 0x70);
}

#if ATTN_TCGEN
// 3-pass split GEMM: (Ahi,Bhi) + (Ahi,Blo) + (Alo,Bhi). 12 dispatches, K=64.
__device__ __forceinline__ void issue_3pass(uint32_t dst, uint64_t ahi, uint64_t alo,
                                            uint64_t bhi, uint64_t blo, bool accum)
{
    #pragma unroll
    for (int p = 0; p < 3; p++) {
        uint64_t A = (p == 2) ? alo : ahi;
        uint64_t B = (p == 1) ? blo : bhi;
        #pragma unroll
        for (int s = 0; s < 4; s++)
            mma_bf16_ss(dst, A + s * 2, B + s * 2, IDESC_BF16,
                        accum || !(p == 0 && s == 0));
    }
}

// Load W [64xK=64] fp32 -> bf16 hi/lo SW128 tile. 128 threads.
__device__ __forceinline__ void load_w_tile(char* smem, uint32_t hi_off,
                                            uint32_t lo_off, const float* W,
                                            int tid)
{
    #pragma unroll 4
    for (int j = 0; j < 8; j++) {
        int u = tid + j * 128;              // 0..1023 float4 units
        int d = u >> 4, e4 = (u & 15) * 4;
        float4 v = *(const float4*)(W + d * 64 + e4);
        __nv_bfloat16 h0 = __float2bfloat16(v.x), h1 = __float2bfloat16(v.y);
        __nv_bfloat16 h2 = __float2bfloat16(v.z), h3 = __float2bfloat16(v.w);
        __nv_bfloat162 hp0, hp1, lp0, lp1;
        hp0.x = h0; hp0.y = h1; hp1.x = h2; hp1.y = h3;
        lp0.x = __float2bfloat16(v.x - __bfloat162float(h0));
        lp0.y = __float2bfloat16(v.y - __bfloat162float(h1));
        lp1.x = __float2bfloat16(v.z - __bfloat162float(h2));
        lp1.y = __float2bfloat16(v.w - __bfloat162float(h3));
        uint2 hp, lp;
        hp.x = *(uint32_t*)&hp0; hp.y = *(uint32_t*)&hp1;
        lp.x = *(uint32_t*)&lp0; lp.y = *(uint32_t*)&lp1;
        uint32_t off = swz((uint32_t)(d * 128 + e4 * 2));
        *(uint2*)(smem + hi_off + off) = hp;
        *(uint2*)(smem + lo_off + off) = lp;
    }
}
#endif

// ============================================================================
// Kernel 1: tensor-core projection, 4 CTAs/SM. grid (256, 8, 3), block 128.
// (unchanged from 446.5us config)
// ============================================================================
#define PX_HI  0
#define PX_LO  16384
#define PW_HI  32768
#define PW_LO  40960
#define PCTRL  49152
#define PSTG   0
#define PSTG_PITCH 528
#define P_TOTAL (PCTRL + 128)

__global__ void __launch_bounds__(128, 4) proj_tc_kernel(
    const float* __restrict__ qin, const float* __restrict__ kin,
    const float* __restrict__ vin, const float* __restrict__ Wq,
    const float* __restrict__ Wk, const float* __restrict__ Wv)
{
    extern __shared__ char smem[];
    const int tid = threadIdx.x;
    const int bx = blockIdx.x, n = blockIdx.y, w = blockIdx.z;
    const float* in; const float* W;
    if (w == 0)      { in = qin; W = Wq; }
    else if (w == 1) { in = kin; W = Wk; }
    else             { in = vin; W = Wv; }
    const bool fmaj = (w < 2);
    const int fb = bx;
    const int fb16 = bx >> 3, tb = bx & 7;

#if ATTN_TCGEN
    const uint32_t sb = smem_u32(smem);
    const int wid = tid >> 5;

    if (wid == 0) {
        TC_ALLOC(sb + PCTRL, 128);
        TC_RELINQ();
    }
    if (tid == 0) MBAR_INIT(sb + PCTRL + 8, 1);
    __syncthreads();
    uint32_t tmem;
    asm volatile("ld.shared.b32 %0, [%1];" : "=r"(tmem) : "r"(sb + PCTRL));
    const uint32_t mb = sb + PCTRL + 8;

    // ---- Load X [128 rows x 64 e] fp32 -> bf16 hi/lo, 1 SW128 tile ----
    #pragma unroll 4
    for (int j = 0; j < 16; j++) {
        int u = tid + j * 128;
        int r = u >> 4, e4 = (u & 15) * 4;
        int t, f;
        if (fmaj) { t = r & 63;            f = fb * 2 + (r >> 6); }
        else      { t = tb * 8 + (r >> 4); f = fb16 * 16 + (r & 15); }
        float4 v = *(const float4*)(in + (((size_t)n * 64 + t) * 512 + f) * 64 + e4);
        __nv_bfloat16 h0 = __float2bfloat16(v.x), h1 = __float2bfloat16(v.y);
        __nv_bfloat16 h2 = __float2bfloat16(v.z), h3 = __float2bfloat16(v.w);
        __nv_bfloat162 hp0, hp1, lp0, lp1;
        hp0.x = h0; hp0.y = h1; hp1.x = h2; hp1.y = h3;
        lp0.x = __float2bfloat16(v.x - __bfloat162float(h0));
        lp0.y = __float2bfloat16(v.y - __bfloat162float(h1));
        lp1.x = __float2bfloat16(v.z - __bfloat162float(h2));
        lp1.y = __float2bfloat16(v.w - __bfloat162float(h3));
        uint2 hp, lp;
        hp.x = *(uint32_t*)&hp0; hp.y = *(uint32_t*)&hp1;
        lp.x = *(uint32_t*)&lp0; lp.y = *(uint32_t*)&lp1;
        uint32_t off = swz((uint32_t)(r * 128 + e4 * 2));
        *(uint2*)(smem + PX_HI + off) = hp;
        *(uint2*)(smem + PX_LO + off) = lp;
    }
    load_w_tile(smem, PW_HI, PW_LO, W, tid);
    FENCE_ASYNC();
    TC_FENCE_BEFORE();
    __syncthreads();

    if (wid == 0) {
        TC_FENCE_AFTER();
        if (elect_one()) {
            issue_3pass(tmem, make_desc(sb + PX_HI), make_desc(sb + PX_LO),
                        make_desc(sb + PW_HI), make_desc(sb + PW_LO), false);
            TC_COMMIT(mb);
        }
    }
    MBAR_WAIT(mb, 0);
    TC_FENCE_AFTER();

    // ---- Stage: pack (hi16<<16|lo16) at [d][row], pitch 528B ----
    {
        char* stg = smem + PSTG;
        #pragma unroll
        for (int cc = 0; cc < 64; cc += 32) {
            uint32_t sreg[32];
            TC_LD_X32(sreg, tmem + cc);
            TC_WAIT_LD();
            #pragma unroll
            for (int d = 0; d < 32; d++) {
                float v = __uint_as_float(sreg[d]);
                __nv_bfloat16 hb = __float2bfloat16(v);
                __nv_bfloat16 lb = __float2bfloat16(v - __bfloat162float(hb));
                uint32_t pk = ((uint32_t)(*(uint16_t*)&hb) << 16)
                            | (uint32_t)(*(uint16_t*)&lb);
                *(uint32_t*)(stg + (cc + d) * PSTG_PITCH + tid * 4) = pk;
            }
        }
    }
    TC_FENCE_BEFORE();
    __syncthreads();

    if (fmaj) {
        int d = tid >> 1, fl = tid & 1;
        const char* src = smem + PSTG + d * PSTG_PITCH + fl * 256;
        __nv_bfloat16* ohi = (w == 0) ? g_Qhi : g_Khi;
        __nv_bfloat16* olo = (w == 0) ? g_Qlo : g_Klo;
        size_t gbase = (((size_t)n * 64 + d) * 512 + fb * 2 + fl) * 64;
        #pragma unroll
        for (int k = 0; k < 16; k++) {
            int kk = (k + d) & 15;
            uint4 pk = *(const uint4*)(src + kk * 16);
            uint2 hp, lp;
            hp.x = (pk.y & 0xFFFF0000u) | (pk.x >> 16);
            hp.y = (pk.w & 0xFFFF0000u) | (pk.z >> 16);
            lp.x = (pk.y << 16) | (pk.x & 0xFFFFu);
            lp.y = (pk.w << 16) | (pk.z & 0xFFFFu);
            *(uint2*)(ohi + gbase + kk * 4) = hp;
            *(uint2*)(olo + gbase + kk * 4) = lp;
        }
    } else {
        #pragma unroll
        for (int q = 0; q < 4; q++) {
            int u2 = tid + q * 128;
            int e = u2 >> 3, tl = u2 & 7;
            const char* src = smem + PSTG + e * PSTG_PITCH + tl * 64;
            uint4 a = *(const uint4*)(src);
            uint4 b = *(const uint4*)(src + 16);
            uint4 c = *(const uint4*)(src + 32);
            uint4 d4 = *(const uint4*)(src + 48);
            uint4 h1, h2v, l1, l2v;
            h1.x = (a.y & 0xFFFF0000u) | (a.x >> 16);
            h1.y = (a.w & 0xFFFF0000u) | (a.z >> 16);
            h1.z = (b.y & 0xFFFF0000u) | (b.x >> 16);
            h1.w = (b.w & 0xFFFF0000u) | (b.z >> 16);
            h2v.x = (c.y & 0xFFFF0000u) | (c.x >> 16);
            h2v.y = (c.w & 0xFFFF0000u) | (c.z >> 16);
            h2v.z = (d4.y & 0xFFFF0000u) | (d4.x >> 16);
            h2v.w = (d4.w & 0xFFFF0000u) | (d4.z >> 16);
            l1.x = (a.y << 16) | (a.x & 0xFFFFu);
            l1.y = (a.w << 16) | (a.z & 0xFFFFu);
            l1.z = (b.y << 16) | (b.x & 0xFFFFu);
            l1.w = (b.w << 16) | (b.z & 0xFFFFu);
            l2v.x = (c.y << 16) | (c.x & 0xFFFFu);
            l2v.y = (c.w << 16) | (c.z & 0xFFFFu);
            l2v.z = (d4.y << 16) | (d4.x & 0xFFFFu);
            l2v.w = (d4.w << 16) | (d4.z & 0xFFFFu);
            size_t ga = ((size_t)(n * 64 + e)) * (64 * 512)
                      + (size_t)(tb * 8 + tl) * 512 + fb16 * 16;
            *(uint4*)(g_Vthi + ga) = h1;
            *(uint4*)(g_Vthi + ga + 8) = h2v;
            *(uint4*)(g_Vtlo + ga) = l1;
            *(uint4*)(g_Vtlo + ga + 8) = l2v;
        }
    }
    __syncthreads();
    if (wid == 0) TC_DEALLOC(tmem, 128);

#else   // ---------------- scalar fallback (non-'a' target) -----------------
    __shared__ float sWf[64 * 64];
    for (int i = tid; i < 4096; i += 128) sWf[i] = W[i];
    __syncthreads();
    for (int idx = tid; idx < 128 * 64; idx += 128) {
        int r = idx >> 6, d = idx & 63;
        int t, f;
        if (fmaj) { t = r & 63;            f = fb * 2 + (r >> 6); }
        else      { t = tb * 8 + (r >> 4); f = fb16 * 16 + (r & 15); }
        const float* xp = in + (((size_t)n * 64 + t) * 512 + f) * 64;
        float s = 0.0f;
        for (int e = 0; e < 64; e++) s = fmaf(xp[e], sWf[d * 64 + e], s);
        __nv_bfloat16 hb = __float2bfloat16(s);
        __nv_bfloat16 lb = __float2bfloat16(s - __bfloat162float(hb));
        if (fmaj) {
            size_t off = (((size_t)n * 64 + d) * 512 + f) * 64 + t;
            if (w == 0) { g_Qhi[off] = hb; g_Qlo[off] = lb; }
            else        { g_Khi[off] = hb; g_Klo[off] = lb; }
        } else {
            size_t off = ((size_t)(n * 64 + d)) * (64 * 512)
                       + (size_t)t * 512 + f;
            g_Vthi[off] = hb; g_Vtlo[off] = lb;
        }
    }
#endif
}

// ============================================================================
// Kernel 2: attention, 2 CTAs/SM with permit fix (446.5us cfg, unchanged).
// ============================================================================
#define SM_QHI  0
#define SM_QLO  16384
#define SM_PHI  32768
#define SM_PLO  49152
#define SM_K    65536
#define SM_V    98304
#define SM_CTRL 114688
#define SM_RED  SM_PHI
#define SM_TOTAL (SM_CTRL + 128)

#if ATTN_TCGEN
__device__ __forceinline__ void load_k_chunk(
    char* smem, const __nv_bfloat16* Khg, const __nv_bfloat16* Klg,
    int c, int kb, int tid)
{
    const __nv_bfloat16* kh = Khg + c * 64 * 64;
    const __nv_bfloat16* kl = Klg + c * 64 * 64;
    char* kbase = smem + SM_K + kb * 16384;
    #pragma unroll
    for (int j = 0; j < 2; j++) {
        int idx = tid + j * 256;
        int r = idx >> 3, c16 = idx & 7;
        uint32_t sw = swz((uint32_t)(r * 128 + c16 * 16));
        uint4 a  = *(const uint4*)(kh + r * 64 + c16 * 8);
        uint4 bb = *(const uint4*)(kl + r * 64 + c16 * 8);
        *(uint4*)(kbase + sw) = a;
        *(uint4*)(kbase + 8192 + sw) = bb;
    }
}

__device__ __forceinline__ void load_v_chunk(
    char* smem, const __nv_bfloat16* Vhg, const __nv_bfloat16* Vlg,
    int c, int tid)
{
    char* vbase = smem + SM_V;
    #pragma unroll
    for (int j = 0; j < 2; j++) {
        int idx = tid + j * 256;
        int r = idx >> 3, c16 = idx & 7;
        uint32_t sw = swz((uint32_t)(r * 128 + c16 * 16));
        uint4 vh = *(const uint4*)(Vhg + (size_t)r * 512 + c * 64 + c16 * 8);
        uint4 vl = *(const uint4*)(Vlg + (size_t)r * 512 + c * 64 + c16 * 8);
        *(uint4*)(vbase + sw) = vh;
        *(uint4*)(vbase + 8192 + sw) = vl;
    }
}
#endif

__global__ void __launch_bounds__(256, 2) attn_tc_kernel()
{
    extern __shared__ char smem[];
    const int tid = threadIdx.x;
    const int qb = blockIdx.x, e = blockIdx.y, n = blockIdx.z;
    const size_t plane = (size_t)(n * 64 + e);
    const size_t qk_base = plane * 512 * 64;
    const __nv_bfloat16* Qhg = g_Qhi + qk_base + (size_t)qb * 128 * 64;
    const __nv_bfloat16* Qlg = g_Qlo + qk_base + (size_t)qb * 128 * 64;
    const __nv_bfloat16* Khg = g_Khi + qk_base;
    const __nv_bfloat16* Klg = g_Klo + qk_base;
    const __nv_bfloat16* Vhg = g_Vthi + plane * 64 * 512;
    const __nv_bfloat16* Vlg = g_Vtlo + plane * 64 * 512;

#if ATTN_TCGEN
    const uint32_t sb = smem_u32(smem);
    const int wid = tid >> 5, lid = tid & 31;
    const int row = (wid & 3) * 32 + lid;
    const int cb  = (wid >> 2) * 32;

    if (wid == 0) {
        TC_ALLOC(sb + SM_CTRL, 256);
        TC_RELINQ();
    }
    if (tid == 0) {
        MBAR_INIT(sb + SM_CTRL + 8, 1);
        MBAR_INIT(sb + SM_CTRL + 16, 1);
        MBAR_INIT(sb + SM_CTRL + 24, 1);
    }
    __syncthreads();
    uint32_t tmem;
    asm volatile("ld.shared.b32 %0, [%1];" : "=r"(tmem) : "r"(sb + SM_CTRL));
    uint32_t tS[2]; tS[0] = tmem; tS[1] = tmem + 64;
    uint32_t mbS[2]; mbS[0] = sb + SM_CTRL + 8; mbS[1] = sb + SM_CTRL + 16;
    const uint32_t mb2 = sb + SM_CTRL + 24;
    const uint32_t tO = tmem + 128;

    #pragma unroll
    for (int j = 0; j < 4; j++) {
        int idx = tid + j * 256;
        int r = idx >> 3, c16 = idx & 7;
        uint32_t sw = swz((uint32_t)(r * 128 + c16 * 16));
        uint4 qh = *(const uint4*)(Qhg + r * 64 + c16 * 8);
        uint4 ql = *(const uint4*)(Qlg + r * 64 + c16 * 8);
        *(uint4*)(smem + SM_QHI + sw) = qh;
        *(uint4*)(smem + SM_QLO + sw) = ql;
    }
    load_k_chunk(smem, Khg, Klg, 0, 0, tid);
    FENCE_ASYNC();
    TC_FENCE_BEFORE();
    __syncthreads();

    const uint64_t dQh = make_desc(sb + SM_QHI), dQl = make_desc(sb + SM_QLO);
    const uint64_t dPh = make_desc(sb + SM_PHI), dPl = make_desc(sb + SM_PLO);
    const uint64_t dVh = make_desc(sb + SM_V),   dVl = make_desc(sb + SM_V + 8192);
    uint64_t dKh[2], dKl[2];
    #pragma unroll
    for (int b = 0; b < 2; b++) {
        dKh[b] = make_desc(sb + SM_K + b * 16384);
        dKl[b] = make_desc(sb + SM_K + b * 16384 + 8192);
    }

    if (wid == 0) {
        TC_FENCE_AFTER();
        if (elect_one()) {
            issue_3pass(tS[0], dQh, dQl, dKh[0], dKl[0], false);
            TC_COMMIT(mbS[0]);
        }
    }

    float l_part = 0.0f;
    uint32_t sreg[32];

    for (int kc = 0; kc < 8; kc++) {
        if (kc > 0) MBAR_WAIT(mb2, (kc - 1) & 1);
        load_v_chunk(smem, Vhg, Vlg, kc, tid);
        if (kc < 7) load_k_chunk(smem, Khg, Klg, kc + 1, (kc + 1) & 1, tid);
        FENCE_ASYNC();
        __syncthreads();
        if (kc < 7 && wid == 0) {
            TC_FENCE_AFTER();
            if (elect_one()) {
                issue_3pass(tS[(kc + 1) & 1], dQh, dQl,
                            dKh[(kc + 1) & 1], dKl[(kc + 1) & 1], false);
                TC_COMMIT(mbS[(kc + 1) & 1]);
            }
        }

        MBAR_WAIT(mbS[kc & 1], (kc >> 1) & 1);
        TC_FENCE_AFTER();
        TC_LD_X32(sreg, tS[kc & 1] + cb);
        TC_WAIT_LD();

        float l_loc = 0.0f;
        #pragma unroll
        for (int c = 0; c < 32; c++) {
            float sv = __uint_as_float(sreg[c]);
            float pe = __expf(sv * 0.125f);
            sreg[c] = __float_as_uint(pe);
            l_loc += pe;
        }
        l_part += l_loc;

        #pragma unroll
        for (int g = 0; g < 4; g++) {
            uint32_t hw[4], lw[4];
            #pragma unroll
            for (int x = 0; x < 4; x++) {
                float p0 = __uint_as_float(sreg[g * 8 + x * 2]);
                float p1 = __uint_as_float(sreg[g * 8 + x * 2 + 1]);
                uint32_t hi;
                asm("cvt.rn.bf16x2.f32 %0, %1, %2;" : "=r"(hi) : "f"(p1), "f"(p0));
                float hf0 = __uint_as_float(hi << 16);
                float hf1 = __uint_as_float(hi & 0xFFFF0000u);
                uint32_t lo;
                asm("cvt.rn.bf16x2.f32 %0, %1, %2;"
                    : "=r"(lo) : "f"(p1 - hf1), "f"(p0 - hf0));
                hw[x] = hi; lw[x] = lo;
            }
            uint32_t sw = swz((uint32_t)(row * 128 + cb * 2 + g * 16));
            *(uint4*)(smem + SM_PHI + sw) = make_uint4(hw[0], hw[1], hw[2], hw[3]);
            *(uint4*)(smem + SM_PLO + sw) = make_uint4(lw[0], lw[1], lw[2], lw[3]);
        }
        TC_FENCE_BEFORE();
        FENCE_ASYNC();
        __syncthreads();

        if (wid == 0) {
            TC_FENCE_AFTER();
            if (elect_one()) {
                issue_3pass(tO, dPh, dPl, dVh, dVl, kc > 0);
                TC_COMMIT(mb2);
            }
        }
    }

    MBAR_WAIT(mb2, 1);
    TC_FENCE_AFTER();

    *(float*)(smem + SM_RED + tid * 4) = l_part;
    TC_LD_X32(sreg, tO + cb);
    TC_WAIT_LD();
    TC_FENCE_BEFORE();
    __syncthreads();
    const float l_sum = l_part + *(float*)(smem + SM_RED + (tid ^ 128) * 4);

    const float inv = 1.0f / l_sum;
    float* Og = g_Op + plane * 512 * 64 + (size_t)qb * 128 * 64
              + (size_t)row * 64 + cb;
    #pragma unroll
    for (int c4 = 0; c4 < 32; c4 += 4) {
        float4 ov = make_float4(__uint_as_float(sreg[c4 + 0]) * inv,
                                __uint_as_float(sreg[c4 + 1]) * inv,
                                __uint_as_float(sreg[c4 + 2]) * inv,
                                __uint_as_float(sreg[c4 + 3]) * inv);
        *(float4*)(Og + c4) = ov;
    }

    __syncthreads();
    if (wid == 0) TC_DEALLOC(tmem, 256);

#else   // ---------------- scalar fallback (non-'a' target) -----------------
    float* sK = (float*)smem;
    float* sV = sK + 64 * 65;

    float qreg[64];
    if (tid < 128) {
        #pragma unroll
        for (int t = 0; t < 64; t++)
            qreg[t] = __bfloat162float(Qhg[tid * 64 + t]) +
                      __bfloat162float(Qlg[tid * 64 + t]);
    }

    float o[64];
    #pragma unroll
    for (int t = 0; t < 64; t++) o[t] = 0.0f;
    float l_sum = 0.0f;

    for (int kc = 0; kc < 8; kc++) {
        __syncthreads();
        for (int i = tid; i < 4096; i += 256) {
            int r = i >> 6, c = i & 63;
            sK[r * 65 + c] = __bfloat162float(Khg[(size_t)(kc * 64 + r) * 64 + c]) +
                             __bfloat162float(Klg[(size_t)(kc * 64 + r) * 64 + c]);
            sV[r * 65 + c] = __bfloat162float(Vhg[(size_t)c * 512 + kc * 64 + r]) +
                             __bfloat162float(Vlg[(size_t)c * 512 + kc * 64 + r]);
        }
        __syncthreads();

        if (tid < 128) {
            for (int k = 0; k < 64; k++) {
                float s = 0.0f;
                #pragma unroll 16
                for (int t = 0; t < 64; t++) s = fmaf(qreg[t], sK[k * 65 + t], s);
                float p = __expf(s * 0.125f);
                l_sum += p;
                #pragma unroll 16
                for (int t = 0; t < 64; t++) o[t] = fmaf(p, sV[k * 65 + t], o[t]);
            }
        }
    }

    if (tid < 128) {
        const float inv = 1.0f / l_sum;
        float* Og = g_Op + plane * 512 * 64 + (size_t)qb * 128 * 64
                  + (size_t)tid * 64;
        #pragma unroll
        for (int c = 0; c < 64; c++) Og[c] = o[c] * inv;
    }
#endif
}

// ============================================================================
// Kernel 3: tensor-core output projection. grid (256 qpair, 8 n), block 128.
// Per CTA: 2 q values x 64 t = M=128 rows, K=64 (e), N=64 (d), 3-pass bf16.
// Op [n][e][q][t] is staged per-q as fp32 [64e][pitch68 t] (coalesced float4
// loads, conflict-free transpose reads), packed bf16 hi/lo into SW128 X tile.
// Epilogue: D (fp32) from TMEM + bias -> out[n][t][q][d], 256B rows.
// smem ~65KB -> 3 CTAs/SM; TMEM 128 cols; permit relinquished at alloc.
// ============================================================================
#define OSTG   0            // fp32 stage: 64 x 68 x 4 = 17408B
#define OSTG_PITCH 68
#define OX_HI  17408        // 16KB SW128 tile
#define OX_LO  33792        // 16KB
#define OW_HI  50176        // 8KB
#define OW_LO  58368        // 8KB
#define OB_    66560        // 256B bias
#define OCTRL  66816        // +0 tmem ptr, +8 mbar
#define O_TOTAL (OCTRL + 128)

__global__ void __launch_bounds__(128, 3) out_tc_kernel(
    const float* __restrict__ Wo, const float* __restrict__ bo,
    float* __restrict__ out)
{
    extern __shared__ char smem[];
    const int tid = threadIdx.x;
    const int qp = blockIdx.x, n = blockIdx.y;

#if ATTN_TCGEN
    const uint32_t sb = smem_u32(smem);
    const int wid = tid >> 5;

    if (wid == 0) {
        TC_ALLOC(sb + OCTRL, 128);
        TC_RELINQ();
    }
    if (tid == 0) MBAR_INIT(sb + OCTRL + 8, 1);
    if (tid < 64) *(float*)(smem + OB_ + tid * 4) = bo[tid];
    __syncthreads();
    uint32_t tmem;
    asm volatile("ld.shared.b32 %0, [%1];" : "=r"(tmem) : "r"(sb + OCTRL));
    const uint32_t mb = sb + OCTRL + 8;

    load_w_tile(smem, OW_HI, OW_LO, Wo, tid);

    // ---- Per q sub-tile: stage Op [64e][64t] fp32, transpose+split to X ----
    float* stg = (float*)(smem + OSTG);
    #pragma unroll
    for (int qi = 0; qi < 2; qi++) {
        const int q = qp * 2 + qi;
        if (qi == 1) __syncthreads();     // X writes of qi=0 done before reuse
        // coalesced load: unit (e, t4)
        #pragma unroll 4
        for (int j = 0; j < 8; j++) {
            int u = tid + j * 128;        // 0..1023
            int e = u >> 4, t4 = (u & 15) * 4;
            float4 v = *(const float4*)(g_Op +
                (((size_t)n * 64 + e) * 512 + q) * 64 + t4);
            float* d = &stg[e * OSTG_PITCH + t4];
            d[0] = v.x; d[1] = v.y; d[2] = v.z; d[3] = v.w;
        }
        __syncthreads();
        // transpose-read + bf16 hi/lo pack: thread -> (row t = tid&63,
        // e-half = tid>>6), writes its 64B half of X row (qi*64 + t)
        {
            const int t = tid & 63, eh = tid >> 6;
            const int r = qi * 64 + t;
            #pragma unroll
            for (int g = 0; g < 4; g++) {
                uint32_t hw[4], lw[4];
                #pragma unroll
                for (int x = 0; x < 4; x++) {
                    int e = eh * 32 + g * 8 + x * 2;
                    float v0 = stg[e * OSTG_PITCH + t];
                    float v1 = stg[(e + 1) * OSTG_PITCH + t];
                    uint32_t hi;
                    asm("cvt.rn.bf16x2.f32 %0, %1, %2;"
                        : "=r"(hi) : "f"(v1), "f"(v0));
                    float hf0 = __uint_as_float(hi << 16);
                    float hf1 = __uint_as_float(hi & 0xFFFF0000u);
                    uint32_t lo;
                    asm("cvt.rn.bf16x2.f32 %0, %1, %2;"
                        : "=r"(lo) : "f"(v1 - hf1), "f"(v0 - hf0));
                    hw[x] = hi; lw[x] = lo;
                }
                uint32_t sw = swz((uint32_t)(r * 128 + eh * 64 + g * 16));
                *(uint4*)(smem + OX_HI + sw) = make_uint4(hw[0], hw[1], hw[2], hw[3]);
                *(uint4*)(smem + OX_LO + sw) = make_uint4(lw[0], lw[1], lw[2], lw[3]);
            }
        }
    }
    FENCE_ASYNC();
    TC_FENCE_BEFORE();
    __syncthreads();

    if (wid == 0) {
        TC_FENCE_AFTER();
        if (elect_one()) {
            issue_3pass(tmem, make_desc(sb + OX_HI), make_desc(sb + OX_LO),
                        make_desc(sb + OW_HI), make_desc(sb + OW_LO), false);
            TC_COMMIT(mb);
        }
    }
    MBAR_WAIT(mb, 0);
    TC_FENCE_AFTER();

    // ---- Epilogue: row = tid (q' = tid>>6, t = tid&63), fp32 + bias ----
    {
        const int qi = tid >> 6, t = tid & 63;
        const int q = qp * 2 + qi;
        float* ob = out + (((size_t)n * 64 + t) * 512 + q) * 64;
        const float* sbias = (const float*)(smem + OB_);
        #pragma unroll
        for (int cc = 0; cc < 64; cc += 32) {
            uint32_t sreg[32];
            TC_LD_X32(sreg, tmem + cc);
            TC_WAIT_LD();
            #pragma unroll
            for (int d4 = 0; d4 < 32; d4 += 4) {
                float4 v = make_float4(
                    __uint_as_float(sreg[d4 + 0]) + sbias[cc + d4 + 0],
                    __uint_as_float(sreg[d4 + 1]) + sbias[cc + d4 + 1],
                    __uint_as_float(sreg[d4 + 2]) + sbias[cc + d4 + 2],
                    __uint_as_float(sreg[d4 + 3]) + sbias[cc + d4 + 3]);
                *(float4*)(ob + cc + d4) = v;
            }
        }
    }
    TC_FENCE_BEFORE();
    __syncthreads();
    if (wid == 0) TC_DEALLOC(tmem, 128);

#else   // ---------------- scalar fallback (non-'a' target) -----------------
    __shared__ float sWf[64 * 64];
    __shared__ float sbv[64];
    for (int i = tid; i < 4096; i += 128) sWf[i] = Wo[i];
    if (tid < 64) sbv[tid] = bo[tid];
    __syncthreads();
    for (int idx = tid; idx < 128 * 64; idx += 128) {
        int r = idx >> 6, d = idx & 63;
        int qi = r >> 6, t = r & 63;
        int q = qp * 2 + qi;
        float s = 0.0f;
        for (int e = 0; e < 64; e++)
            s = fmaf(g_Op[(((size_t)n * 64 + e) * 512 + q) * 64 + t],
                     sWf[d * 64 + e], s);
        out[(((size_t)n * 64 + t) * 512 + q) * 64 + d] = s + sbv[d];
    }
#endif
}

// ---------------------------------------------------------------------------
extern "C" void kernel_launch(void* const* d_in, const int* in_sizes, int n_in,
                              void* d_out, int out_size)
{
    const float* value = (const float*)d_in[0];
    const float* key   = (const float*)d_in[1];
    const float* query = (const float*)d_in[2];
    const float* Wv    = (const float*)d_in[3];
    const float* Wk    = (const float*)d_in[4];
    const float* Wq    = (const float*)d_in[5];
    const float* Wo    = (const float*)d_in[6];
    const float* bo    = (const float*)d_in[7];
    float* out = (float*)d_out;

    cudaFuncSetAttribute(proj_tc_kernel,
                         cudaFuncAttributeMaxDynamicSharedMemorySize, P_TOTAL);
    cudaFuncSetAttribute(attn_tc_kernel,
                         cudaFuncAttributeMaxDynamicSharedMemorySize, SM_TOTAL);
    cudaFuncSetAttribute(out_tc_kernel,
                         cudaFuncAttributeMaxDynamicSharedMemorySize, O_TOTAL);

    dim3 g1(256, 8, 3);
    proj_tc_kernel<<<g1, 128, P_TOTAL>>>(query, key, value, Wq, Wk, Wv);

    dim3 g2(4, 64, 8);
    attn_tc_kernel<<<g2, 256, SM_TOTAL>>>();

    dim3 g3(256, 8);
    out_tc_kernel<<<g3, 128, O_TOTAL>>>(Wo, bo, out);
}

// round 15
// speedup vs baseline: 1.1417x; 1.1417x over previous
#include <cuda_runtime.h>
#include <cuda_bf16.h>
#include <cstdint>
#include <math.h>

// Problem dims: N=8, T=64, F=512, E=64
#define PITCH 65

// Arch-feature gate: tcgen05 exists only on sm_100a/sm_103a ('a' targets).
#if defined(__CUDA_ARCH__) && (defined(__CUDA_ARCH_FEAT_SM103_ALL) || \
    defined(__CUDA_ARCH_FEAT_SM100_ALL) || \
    (defined(__CUDA_ARCH_SPECIFIC__) && (__CUDA_ARCH_SPECIFIC__ >= 1000)))
#define ATTN_TCGEN 1
#else
#define ATTN_TCGEN 0
#endif

#define NELEM (8u * 64u * 512u * 64u)
// Projected Q/K in bf16 hi/lo, layout [n][e][f][t]
__device__ __nv_bfloat16 g_Qhi[NELEM];
__device__ __nv_bfloat16 g_Qlo[NELEM];
__device__ __nv_bfloat16 g_Khi[NELEM];
__device__ __nv_bfloat16 g_Klo[NELEM];
// V transposed, bf16 hi/lo, layout [n][e][t][f] (written directly by proj_tc)
__device__ __nv_bfloat16 g_Vthi[NELEM];
__device__ __nv_bfloat16 g_Vtlo[NELEM];
// Attention output fp32 [n][e][q][t]
__device__ float g_Op[NELEM];

// ============================================================================
// PTX helpers
// ============================================================================
__device__ __forceinline__ uint32_t smem_u32(const void* p) {
    uint32_t a;
    asm("{ .reg .u64 t; cvta.to.shared.u64 t, %1; cvt.u32.u64 %0, t; }"
        : "=r"(a) : "l"(p));
    return a;
}
#if ATTN_TCGEN
__device__ __forceinline__ uint32_t elect_one() {
    uint32_t p;
    asm volatile("{\n\t.reg .pred p;\n\telect.sync _|p, 0xFFFFFFFF;\n\t"
                 "selp.b32 %0, 1, 0, p;\n\t}" : "=r"(p));
    return p;
}
#endif
#define MBAR_INIT(a, c) \
    asm volatile("mbarrier.init.shared.b64 [%0], %1;" :: "r"(a), "r"(c) : "memory")
#define MBAR_WAIT(a, ph) do { \
    uint32_t _m = (a), _p = (ph), _d; \
    asm volatile("{\n\t.reg .pred p;\n\t" \
        "mbarrier.try_wait.parity.acquire.cta.shared::cta.b64 p, [%1], %2;\n\t" \
        "selp.b32 %0, 1, 0, p;\n\t}" : "=r"(_d) : "r"(_m), "r"(_p) : "memory"); \
    if (!_d) { \
        asm volatile("{\n\t.reg .pred P1;\n\tWL_%=: \n\t" \
            "mbarrier.try_wait.parity.acquire.cta.shared::cta.b64 P1, [%0], %1, 0x989680;\n\t" \
            "@P1 bra.uni WD_%=;\n\tbra.uni WL_%=;\n\tWD_%=: \n\t}" \
            :: "r"(_m), "r"(_p) : "memory"); \
    } } while (0)

#define TC_ALLOC(sa, n)  asm volatile( \
    "tcgen05.alloc.cta_group::1.sync.aligned.shared::cta.b32 [%0], %1;" \
    :: "r"(sa), "r"(n) : "memory")
#define TC_DEALLOC(t, n) asm volatile( \
    "tcgen05.dealloc.cta_group::1.sync.aligned.b32 %0, %1;" :: "r"(t), "r"(n))
#define TC_RELINQ() asm volatile("tcgen05.relinquish_alloc_permit.cta_group::1.sync.aligned;")
#define TC_COMMIT(mb) asm volatile( \
    "tcgen05.commit.cta_group::1.mbarrier::arrive::one.shared::cluster.b64 [%0];" \
    :: "r"(mb) : "memory")
#define TC_WAIT_LD() asm volatile("tcgen05.wait::ld.sync.aligned;" ::: "memory")
#define TC_FENCE_BEFORE() asm volatile("tcgen05.fence::before_thread_sync;" ::: "memory")
#define TC_FENCE_AFTER()  asm volatile("tcgen05.fence::after_thread_sync;" ::: "memory")
#define FENCE_ASYNC() asm volatile("fence.proxy.async.shared::cta;" ::: "memory")

#define TC_LD_X32(r, ta) asm volatile( \
    "tcgen05.ld.sync.aligned.32x32b.x32.b32 " \
    "{%0,%1,%2,%3,%4,%5,%6,%7,%8,%9,%10,%11,%12,%13,%14,%15," \
    "%16,%17,%18,%19,%20,%21,%22,%23,%24,%25,%26,%27,%28,%29,%30,%31}, [%32];" \
    : "=r"((r)[0]),"=r"((r)[1]),"=r"((r)[2]),"=r"((r)[3]), \
      "=r"((r)[4]),"=r"((r)[5]),"=r"((r)[6]),"=r"((r)[7]), \
      "=r"((r)[8]),"=r"((r)[9]),"=r"((r)[10]),"=r"((r)[11]), \
      "=r"((r)[12]),"=r"((r)[13]),"=r"((r)[14]),"=r"((r)[15]), \
      "=r"((r)[16]),"=r"((r)[17]),"=r"((r)[18]),"=r"((r)[19]), \
      "=r"((r)[20]),"=r"((r)[21]),"=r"((r)[22]),"=r"((r)[23]), \
      "=r"((r)[24]),"=r"((r)[25]),"=r"((r)[26]),"=r"((r)[27]), \
      "=r"((r)[28]),"=r"((r)[29]),"=r"((r)[30]),"=r"((r)[31]) \
    : "r"(ta))

#if ATTN_TCGEN
__device__ __forceinline__ void mma_bf16_ss(uint32_t d, uint64_t a, uint64_t b,
                                            uint32_t idesc, bool en) {
    uint32_t e = en ? 1u : 0u;
    asm volatile(
        "{\n\t.reg .pred p;\n\tsetp.ne.u32 p, %5, 0;\n\t"
        "tcgen05.mma.cta_group::1.kind::f16 [%0], %1, %2, %3, {%4,%4,%4,%4}, p;\n\t}"
        :: "r"(d), "l"(a), "l"(b), "r"(idesc), "r"(0u), "r"(e) : "memory");
}
#endif

// SMEM desc: SW128, version=1(Blackwell), SBO=64, LBO=1
static __device__ __forceinline__ uint64_t make_desc(uint32_t addr) {
    const uint64_t base = (uint64_t(2) << 61) | (uint64_t(1) << 46) |
                          (uint64_t(64) << 32) | (uint64_t(1) << 16);
    return base | ((uint64_t)(addr >> 4) & 0x3FFF);
}

// idesc kind::f16 bf16: dtype=F32(1<<4), atype=BF16(1<<7), btype=BF16(1<<10),
// N=64 ((64/8)<<17), M=128 ((128/16)<<24)
#define IDESC_BF16 ((1u<<4) | (1u<<7) | (1u<<10) | (8u<<17) | (8u<<24))

__device__ __forceinline__ uint32_t swz(uint32_t off) {
    return off ^ ((off >> 3) & 0x70);
}

#if ATTN_TCGEN
// 3-pass split GEMM: (Ahi,Bhi) + (Ahi,Blo) + (Alo,Bhi). 12 dispatches, K=64.
__device__ __forceinline__ void issue_3pass(uint32_t dst, uint64_t ahi, uint64_t alo,
                                            uint64_t bhi, uint64_t blo, bool accum)
{
    #pragma unroll
    for (int p = 0; p < 3; p++) {
        uint64_t A = (p == 2) ? alo : ahi;
        uint64_t B = (p == 1) ? blo : bhi;
        #pragma unroll
        for (int s = 0; s < 4; s++)
            mma_bf16_ss(dst, A + s * 2, B + s * 2, IDESC_BF16,
                        accum || !(p == 0 && s == 0));
    }
}

// Load W [64xK=64] fp32 -> bf16 hi/lo SW128 tile. 128 threads.
__device__ __forceinline__ void load_w_tile(char* smem, uint32_t hi_off,
                                            uint32_t lo_off, const float* W,
                                            int tid)
{
    #pragma unroll 4
    for (int j = 0; j < 8; j++) {
        int u = tid + j * 128;              // 0..1023 float4 units
        int d = u >> 4, e4 = (u & 15) * 4;
        float4 v = *(const float4*)(W + d * 64 + e4);
        __nv_bfloat16 h0 = __float2bfloat16(v.x), h1 = __float2bfloat16(v.y);
        __nv_bfloat16 h2 = __float2bfloat16(v.z), h3 = __float2bfloat16(v.w);
        __nv_bfloat162 hp0, hp1, lp0, lp1;
        hp0.x = h0; hp0.y = h1; hp1.x = h2; hp1.y = h3;
        lp0.x = __float2bfloat16(v.x - __bfloat162float(h0));
        lp0.y = __float2bfloat16(v.y - __bfloat162float(h1));
        lp1.x = __float2bfloat16(v.z - __bfloat162float(h2));
        lp1.y = __float2bfloat16(v.w - __bfloat162float(h3));
        uint2 hp, lp;
        hp.x = *(uint32_t*)&hp0; hp.y = *(uint32_t*)&hp1;
        lp.x = *(uint32_t*)&lp0; lp.y = *(uint32_t*)&lp1;
        uint32_t off = swz((uint32_t)(d * 128 + e4 * 2));
        *(uint2*)(smem + hi_off + off) = hp;
        *(uint2*)(smem + lo_off + off) = lp;
    }
}
#endif

// ============================================================================
// Kernel 1: tensor-core projection, 4 CTAs/SM. grid (256, 8, 3), block 128.
// Q/K epilogue now writes SEGMENT-granular (16B per lane, 8 lanes per 128B
// output row) -> fully coalesced sectors (was 8B scattered = 4x L2 write amp).
// ============================================================================
#define PX_HI  0
#define PX_LO  16384
#define PW_HI  32768
#define PW_LO  40960
#define PCTRL  49152
#define PSTG   0
#define PSTG_PITCH 528
#define P_TOTAL (PCTRL + 128)

__global__ void __launch_bounds__(128, 4) proj_tc_kernel(
    const float* __restrict__ qin, const float* __restrict__ kin,
    const float* __restrict__ vin, const float* __restrict__ Wq,
    const float* __restrict__ Wk, const float* __restrict__ Wv)
{
    extern __shared__ char smem[];
    const int tid = threadIdx.x;
    const int bx = blockIdx.x, n = blockIdx.y, w = blockIdx.z;
    const float* in; const float* W;
    if (w == 0)      { in = qin; W = Wq; }
    else if (w == 1) { in = kin; W = Wk; }
    else             { in = vin; W = Wv; }
    const bool fmaj = (w < 2);
    const int fb = bx;
    const int fb16 = bx >> 3, tb = bx & 7;

#if ATTN_TCGEN
    const uint32_t sb = smem_u32(smem);
    const int wid = tid >> 5;

    if (wid == 0) {
        TC_ALLOC(sb + PCTRL, 128);
        TC_RELINQ();
    }
    if (tid == 0) MBAR_INIT(sb + PCTRL + 8, 1);
    __syncthreads();
    uint32_t tmem;
    asm volatile("ld.shared.b32 %0, [%1];" : "=r"(tmem) : "r"(sb + PCTRL));
    const uint32_t mb = sb + PCTRL + 8;

    // ---- Load X [128 rows x 64 e] fp32 -> bf16 hi/lo, 1 SW128 tile ----
    #pragma unroll 4
    for (int j = 0; j < 16; j++) {
        int u = tid + j * 128;
        int r = u >> 4, e4 = (u & 15) * 4;
        int t, f;
        if (fmaj) { t = r & 63;            f = fb * 2 + (r >> 6); }
        else      { t = tb * 8 + (r >> 4); f = fb16 * 16 + (r & 15); }
        float4 v = *(const float4*)(in + (((size_t)n * 64 + t) * 512 + f) * 64 + e4);
        __nv_bfloat16 h0 = __float2bfloat16(v.x), h1 = __float2bfloat16(v.y);
        __nv_bfloat16 h2 = __float2bfloat16(v.z), h3 = __float2bfloat16(v.w);
        __nv_bfloat162 hp0, hp1, lp0, lp1;
        hp0.x = h0; hp0.y = h1; hp1.x = h2; hp1.y = h3;
        lp0.x = __float2bfloat16(v.x - __bfloat162float(h0));
        lp0.y = __float2bfloat16(v.y - __bfloat162float(h1));
        lp1.x = __float2bfloat16(v.z - __bfloat162float(h2));
        lp1.y = __float2bfloat16(v.w - __bfloat162float(h3));
        uint2 hp, lp;
        hp.x = *(uint32_t*)&hp0; hp.y = *(uint32_t*)&hp1;
        lp.x = *(uint32_t*)&lp0; lp.y = *(uint32_t*)&lp1;
        uint32_t off = swz((uint32_t)(r * 128 + e4 * 2));
        *(uint2*)(smem + PX_HI + off) = hp;
        *(uint2*)(smem + PX_LO + off) = lp;
    }
    load_w_tile(smem, PW_HI, PW_LO, W, tid);
    FENCE_ASYNC();
    TC_FENCE_BEFORE();
    __syncthreads();

    if (wid == 0) {
        TC_FENCE_AFTER();
        if (elect_one()) {
            issue_3pass(tmem, make_desc(sb + PX_HI), make_desc(sb + PX_LO),
                        make_desc(sb + PW_HI), make_desc(sb + PW_LO), false);
            TC_COMMIT(mb);
        }
    }
    MBAR_WAIT(mb, 0);
    TC_FENCE_AFTER();

    // ---- Stage: pack (hi16<<16|lo16) at [d][row], pitch 528B ----
    {
        char* stg = smem + PSTG;
        #pragma unroll
        for (int cc = 0; cc < 64; cc += 32) {
            uint32_t sreg[32];
            TC_LD_X32(sreg, tmem + cc);
            TC_WAIT_LD();
            #pragma unroll
            for (int d = 0; d < 32; d++) {
                float v = __uint_as_float(sreg[d]);
                __nv_bfloat16 hb = __float2bfloat16(v);
                __nv_bfloat16 lb = __float2bfloat16(v - __bfloat162float(hb));
                uint32_t pk = ((uint32_t)(*(uint16_t*)&hb) << 16)
                            | (uint32_t)(*(uint16_t*)&lb);
                *(uint32_t*)(stg + (cc + d) * PSTG_PITCH + tid * 4) = pk;
            }
        }
    }
    TC_FENCE_BEFORE();
    __syncthreads();

    if (fmaj) {
        // Coalesced epilogue: unit u = (row, seg). row = u>>3 picks output
        // row (d = row>>1, fl = row&1); seg = u&7 picks its 16B segment.
        // 8 consecutive lanes cover one 128B row -> full-sector writes.
        __nv_bfloat16* ohi = (w == 0) ? g_Qhi : g_Khi;
        __nv_bfloat16* olo = (w == 0) ? g_Qlo : g_Klo;
        #pragma unroll
        for (int j = 0; j < 8; j++) {
            int u = tid + j * 128;              // 0..1023
            int rrow = u >> 3, seg = u & 7;
            int d = rrow >> 1, fl = rrow & 1;
            const char* src = smem + PSTG + d * PSTG_PITCH + fl * 256 + seg * 32;
            uint4 a = *(const uint4*)(src);
            uint4 b = *(const uint4*)(src + 16);
            uint4 hp, lp;
            hp.x = (a.y & 0xFFFF0000u) | (a.x >> 16);
            hp.y = (a.w & 0xFFFF0000u) | (a.z >> 16);
            hp.z = (b.y & 0xFFFF0000u) | (b.x >> 16);
            hp.w = (b.w & 0xFFFF0000u) | (b.z >> 16);
            lp.x = (a.y << 16) | (a.x & 0xFFFFu);
            lp.y = (a.w << 16) | (a.z & 0xFFFFu);
            lp.z = (b.y << 16) | (b.x & 0xFFFFu);
            lp.w = (b.w << 16) | (b.z & 0xFFFFu);
            size_t gbase = (((size_t)n * 64 + d) * 512 + fb * 2 + fl) * 64
                         + seg * 8;
            *(uint4*)(ohi + gbase) = hp;
            *(uint4*)(olo + gbase) = lp;
        }
    } else {
        #pragma unroll
        for (int q = 0; q < 4; q++) {
            int u2 = tid + q * 128;
            int e = u2 >> 3, tl = u2 & 7;
            const char* src = smem + PSTG + e * PSTG_PITCH + tl * 64;
            uint4 a = *(const uint4*)(src);
            uint4 b = *(const uint4*)(src + 16);
            uint4 c = *(const uint4*)(src + 32);
            uint4 d4 = *(const uint4*)(src + 48);
            uint4 h1, h2v, l1, l2v;
            h1.x = (a.y & 0xFFFF0000u) | (a.x >> 16);
            h1.y = (a.w & 0xFFFF0000u) | (a.z >> 16);
            h1.z = (b.y & 0xFFFF0000u) | (b.x >> 16);
            h1.w = (b.w & 0xFFFF0000u) | (b.z >> 16);
            h2v.x = (c.y & 0xFFFF0000u) | (c.x >> 16);
            h2v.y = (c.w & 0xFFFF0000u) | (c.z >> 16);
            h2v.z = (d4.y & 0xFFFF0000u) | (d4.x >> 16);
            h2v.w = (d4.w & 0xFFFF0000u) | (d4.z >> 16);
            l1.x = (a.y << 16) | (a.x & 0xFFFFu);
            l1.y = (a.w << 16) | (a.z & 0xFFFFu);
            l1.z = (b.y << 16) | (b.x & 0xFFFFu);
            l1.w = (b.w << 16) | (b.z & 0xFFFFu);
            l2v.x = (c.y << 16) | (c.x & 0xFFFFu);
            l2v.y = (c.w << 16) | (c.z & 0xFFFFu);
            l2v.z = (d4.y << 16) | (d4.x & 0xFFFFu);
            l2v.w = (d4.w << 16) | (d4.z & 0xFFFFu);
            size_t ga = ((size_t)(n * 64 + e)) * (64 * 512)
                      + (size_t)(tb * 8 + tl) * 512 + fb16 * 16;
            *(uint4*)(g_Vthi + ga) = h1;
            *(uint4*)(g_Vthi + ga + 8) = h2v;
            *(uint4*)(g_Vtlo + ga) = l1;
            *(uint4*)(g_Vtlo + ga + 8) = l2v;
        }
    }
    __syncthreads();
    if (wid == 0) TC_DEALLOC(tmem, 128);

#else   // ---------------- scalar fallback (non-'a' target) -----------------
    __shared__ float sWf[64 * 64];
    for (int i = tid; i < 4096; i += 128) sWf[i] = W[i];
    __syncthreads();
    for (int idx = tid; idx < 128 * 64; idx += 128) {
        int r = idx >> 6, d = idx & 63;
        int t, f;
        if (fmaj) { t = r & 63;            f = fb * 2 + (r >> 6); }
        else      { t = tb * 8 + (r >> 4); f = fb16 * 16 + (r & 15); }
        const float* xp = in + (((size_t)n * 64 + t) * 512 + f) * 64;
        float s = 0.0f;
        for (int e = 0; e < 64; e++) s = fmaf(xp[e], sWf[d * 64 + e], s);
        __nv_bfloat16 hb = __float2bfloat16(s);
        __nv_bfloat16 lb = __float2bfloat16(s - __bfloat162float(hb));
        if (fmaj) {
            size_t off = (((size_t)n * 64 + d) * 512 + f) * 64 + t;
            if (w == 0) { g_Qhi[off] = hb; g_Qlo[off] = lb; }
            else        { g_Khi[off] = hb; g_Klo[off] = lb; }
        } else {
            size_t off = ((size_t)(n * 64 + d)) * (64 * 512)
                       + (size_t)t * 512 + f;
            g_Vthi[off] = hb; g_Vtlo[off] = lb;
        }
    }
#endif
}

// ============================================================================
// Kernel 2: attention, 2 CTAs/SM with permit fix (446.5us cfg, unchanged).
// ============================================================================
#define SM_QHI  0
#define SM_QLO  16384
#define SM_PHI  32768
#define SM_PLO  49152
#define SM_K    65536
#define SM_V    98304
#define SM_CTRL 114688
#define SM_RED  SM_PHI
#define SM_TOTAL (SM_CTRL + 128)

#if ATTN_TCGEN
__device__ __forceinline__ void load_k_chunk(
    char* smem, const __nv_bfloat16* Khg, const __nv_bfloat16* Klg,
    int c, int kb, int tid)
{
    const __nv_bfloat16* kh = Khg + c * 64 * 64;
    const __nv_bfloat16* kl = Klg + c * 64 * 64;
    char* kbase = smem + SM_K + kb * 16384;
    #pragma unroll
    for (int j = 0; j < 2; j++) {
        int idx = tid + j * 256;
        int r = idx >> 3, c16 = idx & 7;
        uint32_t sw = swz((uint32_t)(r * 128 + c16 * 16));
        uint4 a  = *(const uint4*)(kh + r * 64 + c16 * 8);
        uint4 bb = *(const uint4*)(kl + r * 64 + c16 * 8);
        *(uint4*)(kbase + sw) = a;
        *(uint4*)(kbase + 8192 + sw) = bb;
    }
}

__device__ __forceinline__ void load_v_chunk(
    char* smem, const __nv_bfloat16* Vhg, const __nv_bfloat16* Vlg,
    int c, int tid)
{
    char* vbase = smem + SM_V;
    #pragma unroll
    for (int j = 0; j < 2; j++) {
        int idx = tid + j * 256;
        int r = idx >> 3, c16 = idx & 7;
        uint32_t sw = swz((uint32_t)(r * 128 + c16 * 16));
        uint4 vh = *(const uint4*)(Vhg + (size_t)r * 512 + c * 64 + c16 * 8);
        uint4 vl = *(const uint4*)(Vlg + (size_t)r * 512 + c * 64 + c16 * 8);
        *(uint4*)(vbase + sw) = vh;
        *(uint4*)(vbase + 8192 + sw) = vl;
    }
}
#endif

__global__ void __launch_bounds__(256, 2) attn_tc_kernel()
{
    extern __shared__ char smem[];
    const int tid = threadIdx.x;
    const int qb = blockIdx.x, e = blockIdx.y, n = blockIdx.z;
    const size_t plane = (size_t)(n * 64 + e);
    const size_t qk_base = plane * 512 * 64;
    const __nv_bfloat16* Qhg = g_Qhi + qk_base + (size_t)qb * 128 * 64;
    const __nv_bfloat16* Qlg = g_Qlo + qk_base + (size_t)qb * 128 * 64;
    const __nv_bfloat16* Khg = g_Khi + qk_base;
    const __nv_bfloat16* Klg = g_Klo + qk_base;
    const __nv_bfloat16* Vhg = g_Vthi + plane * 64 * 512;
    const __nv_bfloat16* Vlg = g_Vtlo + plane * 64 * 512;

#if ATTN_TCGEN
    const uint32_t sb = smem_u32(smem);
    const int wid = tid >> 5, lid = tid & 31;
    const int row = (wid & 3) * 32 + lid;
    const int cb  = (wid >> 2) * 32;

    if (wid == 0) {
        TC_ALLOC(sb + SM_CTRL, 256);
        TC_RELINQ();
    }
    if (tid == 0) {
        MBAR_INIT(sb + SM_CTRL + 8, 1);
        MBAR_INIT(sb + SM_CTRL + 16, 1);
        MBAR_INIT(sb + SM_CTRL + 24, 1);
    }
    __syncthreads();
    uint32_t tmem;
    asm volatile("ld.shared.b32 %0, [%1];" : "=r"(tmem) : "r"(sb + SM_CTRL));
    uint32_t tS[2]; tS[0] = tmem; tS[1] = tmem + 64;
    uint32_t mbS[2]; mbS[0] = sb + SM_CTRL + 8; mbS[1] = sb + SM_CTRL + 16;
    const uint32_t mb2 = sb + SM_CTRL + 24;
    const uint32_t tO = tmem + 128;

    #pragma unroll
    for (int j = 0; j < 4; j++) {
        int idx = tid + j * 256;
        int r = idx >> 3, c16 = idx & 7;
        uint32_t sw = swz((uint32_t)(r * 128 + c16 * 16));
        uint4 qh = *(const uint4*)(Qhg + r * 64 + c16 * 8);
        uint4 ql = *(const uint4*)(Qlg + r * 64 + c16 * 8);
        *(uint4*)(smem + SM_QHI + sw) = qh;
        *(uint4*)(smem + SM_QLO + sw) = ql;
    }
    load_k_chunk(smem, Khg, Klg, 0, 0, tid);
    FENCE_ASYNC();
    TC_FENCE_BEFORE();
    __syncthreads();

    const uint64_t dQh = make_desc(sb + SM_QHI), dQl = make_desc(sb + SM_QLO);
    const uint64_t dPh = make_desc(sb + SM_PHI), dPl = make_desc(sb + SM_PLO);
    const uint64_t dVh = make_desc(sb + SM_V),   dVl = make_desc(sb + SM_V + 8192);
    uint64_t dKh[2], dKl[2];
    #pragma unroll
    for (int b = 0; b < 2; b++) {
        dKh[b] = make_desc(sb + SM_K + b * 16384);
        dKl[b] = make_desc(sb + SM_K + b * 16384 + 8192);
    }

    if (wid == 0) {
        TC_FENCE_AFTER();
        if (elect_one()) {
            issue_3pass(tS[0], dQh, dQl, dKh[0], dKl[0], false);
            TC_COMMIT(mbS[0]);
        }
    }

    float l_part = 0.0f;
    uint32_t sreg[32];

    for (int kc = 0; kc < 8; kc++) {
        if (kc > 0) MBAR_WAIT(mb2, (kc - 1) & 1);
        load_v_chunk(smem, Vhg, Vlg, kc, tid);
        if (kc < 7) load_k_chunk(smem, Khg, Klg, kc + 1, (kc + 1) & 1, tid);
        FENCE_ASYNC();
        __syncthreads();
        if (kc < 7 && wid == 0) {
            TC_FENCE_AFTER();
            if (elect_one()) {
                issue_3pass(tS[(kc + 1) & 1], dQh, dQl,
                            dKh[(kc + 1) & 1], dKl[(kc + 1) & 1], false);
                TC_COMMIT(mbS[(kc + 1) & 1]);
            }
        }

        MBAR_WAIT(mbS[kc & 1], (kc >> 1) & 1);
        TC_FENCE_AFTER();
        TC_LD_X32(sreg, tS[kc & 1] + cb);
        TC_WAIT_LD();

        float l_loc = 0.0f;
        #pragma unroll
        for (int c = 0; c < 32; c++) {
            float sv = __uint_as_float(sreg[c]);
            float pe = __expf(sv * 0.125f);
            sreg[c] = __float_as_uint(pe);
            l_loc += pe;
        }
        l_part += l_loc;

        #pragma unroll
        for (int g = 0; g < 4; g++) {
            uint32_t hw[4], lw[4];
            #pragma unroll
            for (int x = 0; x < 4; x++) {
                float p0 = __uint_as_float(sreg[g * 8 + x * 2]);
                float p1 = __uint_as_float(sreg[g * 8 + x * 2 + 1]);
                uint32_t hi;
                asm("cvt.rn.bf16x2.f32 %0, %1, %2;" : "=r"(hi) : "f"(p1), "f"(p0));
                float hf0 = __uint_as_float(hi << 16);
                float hf1 = __uint_as_float(hi & 0xFFFF0000u);
                uint32_t lo;
                asm("cvt.rn.bf16x2.f32 %0, %1, %2;"
                    : "=r"(lo) : "f"(p1 - hf1), "f"(p0 - hf0));
                hw[x] = hi; lw[x] = lo;
            }
            uint32_t sw = swz((uint32_t)(row * 128 + cb * 2 + g * 16));
            *(uint4*)(smem + SM_PHI + sw) = make_uint4(hw[0], hw[1], hw[2], hw[3]);
            *(uint4*)(smem + SM_PLO + sw) = make_uint4(lw[0], lw[1], lw[2], lw[3]);
        }
        TC_FENCE_BEFORE();
        FENCE_ASYNC();
        __syncthreads();

        if (wid == 0) {
            TC_FENCE_AFTER();
            if (elect_one()) {
                issue_3pass(tO, dPh, dPl, dVh, dVl, kc > 0);
                TC_COMMIT(mb2);
            }
        }
    }

    MBAR_WAIT(mb2, 1);
    TC_FENCE_AFTER();

    *(float*)(smem + SM_RED + tid * 4) = l_part;
    TC_LD_X32(sreg, tO + cb);
    TC_WAIT_LD();
    TC_FENCE_BEFORE();
    __syncthreads();
    const float l_sum = l_part + *(float*)(smem + SM_RED + (tid ^ 128) * 4);

    const float inv = 1.0f / l_sum;
    float* Og = g_Op + plane * 512 * 64 + (size_t)qb * 128 * 64
              + (size_t)row * 64 + cb;
    #pragma unroll
    for (int c4 = 0; c4 < 32; c4 += 4) {
        float4 ov = make_float4(__uint_as_float(sreg[c4 + 0]) * inv,
                                __uint_as_float(sreg[c4 + 1]) * inv,
                                __uint_as_float(sreg[c4 + 2]) * inv,
                                __uint_as_float(sreg[c4 + 3]) * inv);
        *(float4*)(Og + c4) = ov;
    }

    __syncthreads();
    if (wid == 0) TC_DEALLOC(tmem, 256);

#else   // ---------------- scalar fallback (non-'a' target) -----------------
    float* sK = (float*)smem;
    float* sV = sK + 64 * 65;

    float qreg[64];
    if (tid < 128) {
        #pragma unroll
        for (int t = 0; t < 64; t++)
            qreg[t] = __bfloat162float(Qhg[tid * 64 + t]) +
                      __bfloat162float(Qlg[tid * 64 + t]);
    }

    float o[64];
    #pragma unroll
    for (int t = 0; t < 64; t++) o[t] = 0.0f;
    float l_sum = 0.0f;

    for (int kc = 0; kc < 8; kc++) {
        __syncthreads();
        for (int i = tid; i < 4096; i += 256) {
            int r = i >> 6, c = i & 63;
            sK[r * 65 + c] = __bfloat162float(Khg[(size_t)(kc * 64 + r) * 64 + c]) +
                             __bfloat162float(Klg[(size_t)(kc * 64 + r) * 64 + c]);
            sV[r * 65 + c] = __bfloat162float(Vhg[(size_t)c * 512 + kc * 64 + r]) +
                             __bfloat162float(Vlg[(size_t)c * 512 + kc * 64 + r]);
        }
        __syncthreads();

        if (tid < 128) {
            for (int k = 0; k < 64; k++) {
                float s = 0.0f;
                #pragma unroll 16
                for (int t = 0; t < 64; t++) s = fmaf(qreg[t], sK[k * 65 + t], s);
                float p = __expf(s * 0.125f);
                l_sum += p;
                #pragma unroll 16
                for (int t = 0; t < 64; t++) o[t] = fmaf(p, sV[k * 65 + t], o[t]);
            }
        }
    }

    if (tid < 128) {
        const float inv = 1.0f / l_sum;
        float* Og = g_Op + plane * 512 * 64 + (size_t)qb * 128 * 64
                  + (size_t)tid * 64;
        #pragma unroll
        for (int c = 0; c < 64; c++) Og[c] = o[c] * inv;
    }
#endif
}

// ============================================================================
// Kernel 3: tensor-core output projection (unchanged from round 14).
// ============================================================================
#define OSTG   0
#define OSTG_PITCH 68
#define OX_HI  17408
#define OX_LO  33792
#define OW_HI  50176
#define OW_LO  58368
#define OB_    66560
#define OCTRL  66816
#define O_TOTAL (OCTRL + 128)

__global__ void __launch_bounds__(128, 3) out_tc_kernel(
    const float* __restrict__ Wo, const float* __restrict__ bo,
    float* __restrict__ out)
{
    extern __shared__ char smem[];
    const int tid = threadIdx.x;
    const int qp = blockIdx.x, n = blockIdx.y;

#if ATTN_TCGEN
    const uint32_t sb = smem_u32(smem);
    const int wid = tid >> 5;

    if (wid == 0) {
        TC_ALLOC(sb + OCTRL, 128);
        TC_RELINQ();
    }
    if (tid == 0) MBAR_INIT(sb + OCTRL + 8, 1);
    if (tid < 64) *(float*)(smem + OB_ + tid * 4) = bo[tid];
    __syncthreads();
    uint32_t tmem;
    asm volatile("ld.shared.b32 %0, [%1];" : "=r"(tmem) : "r"(sb + OCTRL));
    const uint32_t mb = sb + OCTRL + 8;

    load_w_tile(smem, OW_HI, OW_LO, Wo, tid);

    float* stg = (float*)(smem + OSTG);
    #pragma unroll
    for (int qi = 0; qi < 2; qi++) {
        const int q = qp * 2 + qi;
        if (qi == 1) __syncthreads();
        #pragma unroll 4
        for (int j = 0; j < 8; j++) {
            int u = tid + j * 128;
            int e = u >> 4, t4 = (u & 15) * 4;
            float4 v = *(const float4*)(g_Op +
                (((size_t)n * 64 + e) * 512 + q) * 64 + t4);
            float* d = &stg[e * OSTG_PITCH + t4];
            d[0] = v.x; d[1] = v.y; d[2] = v.z; d[3] = v.w;
        }
        __syncthreads();
        {
            const int t = tid & 63, eh = tid >> 6;
            const int r = qi * 64 + t;
            #pragma unroll
            for (int g = 0; g < 4; g++) {
                uint32_t hw[4], lw[4];
                #pragma unroll
                for (int x = 0; x < 4; x++) {
                    int e = eh * 32 + g * 8 + x * 2;
                    float v0 = stg[e * OSTG_PITCH + t];
                    float v1 = stg[(e + 1) * OSTG_PITCH + t];
                    uint32_t hi;
                    asm("cvt.rn.bf16x2.f32 %0, %1, %2;"
                        : "=r"(hi) : "f"(v1), "f"(v0));
                    float hf0 = __uint_as_float(hi << 16);
                    float hf1 = __uint_as_float(hi & 0xFFFF0000u);
                    uint32_t lo;
                    asm("cvt.rn.bf16x2.f32 %0, %1, %2;"
                        : "=r"(lo) : "f"(v1 - hf1), "f"(v0 - hf0));
                    hw[x] = hi; lw[x] = lo;
                }
                uint32_t sw = swz((uint32_t)(r * 128 + eh * 64 + g * 16));
                *(uint4*)(smem + OX_HI + sw) = make_uint4(hw[0], hw[1], hw[2], hw[3]);
                *(uint4*)(smem + OX_LO + sw) = make_uint4(lw[0], lw[1], lw[2], lw[3]);
            }
        }
    }
    FENCE_ASYNC();
    TC_FENCE_BEFORE();
    __syncthreads();

    if (wid == 0) {
        TC_FENCE_AFTER();
        if (elect_one()) {
            issue_3pass(tmem, make_desc(sb + OX_HI), make_desc(sb + OX_LO),
                        make_desc(sb + OW_HI), make_desc(sb + OW_LO), false);
            TC_COMMIT(mb);
        }
    }
    MBAR_WAIT(mb, 0);
    TC_FENCE_AFTER();

    {
        const int qi = tid >> 6, t = tid & 63;
        const int q = qp * 2 + qi;
        float* ob = out + (((size_t)n * 64 + t) * 512 + q) * 64;
        const float* sbias = (const float*)(smem + OB_);
        #pragma unroll
        for (int cc = 0; cc < 64; cc += 32) {
            uint32_t sreg[32];
            TC_LD_X32(sreg, tmem + cc);
            TC_WAIT_LD();
            #pragma unroll
            for (int d4 = 0; d4 < 32; d4 += 4) {
                float4 v = make_float4(
                    __uint_as_float(sreg[d4 + 0]) + sbias[cc + d4 + 0],
                    __uint_as_float(sreg[d4 + 1]) + sbias[cc + d4 + 1],
                    __uint_as_float(sreg[d4 + 2]) + sbias[cc + d4 + 2],
                    __uint_as_float(sreg[d4 + 3]) + sbias[cc + d4 + 3]);
                *(float4*)(ob + cc + d4) = v;
            }
        }
    }
    TC_FENCE_BEFORE();
    __syncthreads();
    if (wid == 0) TC_DEALLOC(tmem, 128);

#else   // ---------------- scalar fallback (non-'a' target) -----------------
    __shared__ float sWf[64 * 64];
    __shared__ float sbv[64];
    for (int i = tid; i < 4096; i += 128) sWf[i] = Wo[i];
    if (tid < 64) sbv[tid] = bo[tid];
    __syncthreads();
    for (int idx = tid; idx < 128 * 64; idx += 128) {
        int r = idx >> 6, d = idx & 63;
        int qi = r >> 6, t = r & 63;
        int q = qp * 2 + qi;
        float s = 0.0f;
        for (int e = 0; e < 64; e++)
            s = fmaf(g_Op[(((size_t)n * 64 + e) * 512 + q) * 64 + t],
                     sWf[d * 64 + e], s);
        out[(((size_t)n * 64 + t) * 512 + q) * 64 + d] = s + sbv[d];
    }
#endif
}

// ---------------------------------------------------------------------------
extern "C" void kernel_launch(void* const* d_in, const int* in_sizes, int n_in,
                              void* d_out, int out_size)
{
    const float* value = (const float*)d_in[0];
    const float* key   = (const float*)d_in[1];
    const float* query = (const float*)d_in[2];
    const float* Wv    = (const float*)d_in[3];
    const float* Wk    = (const float*)d_in[4];
    const float* Wq    = (const float*)d_in[5];
    const float* Wo    = (const float*)d_in[6];
    const float* bo    = (const float*)d_in[7];
    float* out = (float*)d_out;

    cudaFuncSetAttribute(proj_tc_kernel,
                         cudaFuncAttributeMaxDynamicSharedMemorySize, P_TOTAL);
    cudaFuncSetAttribute(attn_tc_kernel,
                         cudaFuncAttributeMaxDynamicSharedMemorySize, SM_TOTAL);
    cudaFuncSetAttribute(out_tc_kernel,
                         cudaFuncAttributeMaxDynamicSharedMemorySize, O_TOTAL);

    dim3 g1(256, 8, 3);
    proj_tc_kernel<<<g1, 128, P_TOTAL>>>(query, key, value, Wq, Wk, Wv);

    dim3 g2(4, 64, 8);
    attn_tc_kernel<<<g2, 256, SM_TOTAL>>>();

    dim3 g3(256, 8);
    out_tc_kernel<<<g3, 128, O_TOTAL>>>(Wo, bo, out);
}

// round 16
// speedup vs baseline: 1.1921x; 1.0441x over previous
#include <cuda_runtime.h>
#include <cuda_bf16.h>
#include <cstdint>
#include <math.h>

// Problem dims: N=8, T=64, F=512, E=64
#define PITCH 65

// Arch-feature gate: tcgen05 exists only on sm_100a/sm_103a ('a' targets).
#if defined(__CUDA_ARCH__) && (defined(__CUDA_ARCH_FEAT_SM103_ALL) || \
    defined(__CUDA_ARCH_FEAT_SM100_ALL) || \
    (defined(__CUDA_ARCH_SPECIFIC__) && (__CUDA_ARCH_SPECIFIC__ >= 1000)))
#define ATTN_TCGEN 1
#else
#define ATTN_TCGEN 0
#endif

#define NELEM (8u * 64u * 512u * 64u)
// Projected Q/K in bf16 hi/lo, layout [n][e][f][t]
__device__ __nv_bfloat16 g_Qhi[NELEM];
__device__ __nv_bfloat16 g_Qlo[NELEM];
__device__ __nv_bfloat16 g_Khi[NELEM];
__device__ __nv_bfloat16 g_Klo[NELEM];
// V transposed, bf16 hi/lo, layout [n][e][t][f] (written directly by proj_tc)
__device__ __nv_bfloat16 g_Vthi[NELEM];
__device__ __nv_bfloat16 g_Vtlo[NELEM];
// Attention output fp32 [n][e][q][t]
__device__ float g_Op[NELEM];

// ============================================================================
// PTX helpers
// ============================================================================
__device__ __forceinline__ uint32_t smem_u32(const void* p) {
    uint32_t a;
    asm("{ .reg .u64 t; cvta.to.shared.u64 t, %1; cvt.u32.u64 %0, t; }"
        : "=r"(a) : "l"(p));
    return a;
}
#if ATTN_TCGEN
__device__ __forceinline__ uint32_t elect_one() {
    uint32_t p;
    asm volatile("{\n\t.reg .pred p;\n\telect.sync _|p, 0xFFFFFFFF;\n\t"
                 "selp.b32 %0, 1, 0, p;\n\t}" : "=r"(p));
    return p;
}
#endif
#define MBAR_INIT(a, c) \
    asm volatile("mbarrier.init.shared.b64 [%0], %1;" :: "r"(a), "r"(c) : "memory")
#define MBAR_WAIT(a, ph) do { \
    uint32_t _m = (a), _p = (ph), _d; \
    asm volatile("{\n\t.reg .pred p;\n\t" \
        "mbarrier.try_wait.parity.acquire.cta.shared::cta.b64 p, [%1], %2;\n\t" \
        "selp.b32 %0, 1, 0, p;\n\t}" : "=r"(_d) : "r"(_m), "r"(_p) : "memory"); \
    if (!_d) { \
        asm volatile("{\n\t.reg .pred P1;\n\tWL_%=: \n\t" \
            "mbarrier.try_wait.parity.acquire.cta.shared::cta.b64 P1, [%0], %1, 0x989680;\n\t" \
            "@P1 bra.uni WD_%=;\n\tbra.uni WL_%=;\n\tWD_%=: \n\t}" \
            :: "r"(_m), "r"(_p) : "memory"); \
    } } while (0)

#define TC_ALLOC(sa, n)  asm volatile( \
    "tcgen05.alloc.cta_group::1.sync.aligned.shared::cta.b32 [%0], %1;" \
    :: "r"(sa), "r"(n) : "memory")
#define TC_DEALLOC(t, n) asm volatile( \
    "tcgen05.dealloc.cta_group::1.sync.aligned.b32 %0, %1;" :: "r"(t), "r"(n))
#define TC_RELINQ() asm volatile("tcgen05.relinquish_alloc_permit.cta_group::1.sync.aligned;")
#define TC_COMMIT(mb) asm volatile( \
    "tcgen05.commit.cta_group::1.mbarrier::arrive::one.shared::cluster.b64 [%0];" \
    :: "r"(mb) : "memory")
#define TC_WAIT_LD() asm volatile("tcgen05.wait::ld.sync.aligned;" ::: "memory")
#define TC_WAIT_ST() asm volatile("tcgen05.wait::st.sync.aligned;" ::: "memory")
#define TC_FENCE_BEFORE() asm volatile("tcgen05.fence::before_thread_sync;" ::: "memory")
#define TC_FENCE_AFTER()  asm volatile("tcgen05.fence::after_thread_sync;" ::: "memory")
#define FENCE_ASYNC() asm volatile("fence.proxy.async.shared::cta;" ::: "memory")

#define TC_LD_X32(r, ta) asm volatile( \
    "tcgen05.ld.sync.aligned.32x32b.x32.b32 " \
    "{%0,%1,%2,%3,%4,%5,%6,%7,%8,%9,%10,%11,%12,%13,%14,%15," \
    "%16,%17,%18,%19,%20,%21,%22,%23,%24,%25,%26,%27,%28,%29,%30,%31}, [%32];" \
    : "=r"((r)[0]),"=r"((r)[1]),"=r"((r)[2]),"=r"((r)[3]), \
      "=r"((r)[4]),"=r"((r)[5]),"=r"((r)[6]),"=r"((r)[7]), \
      "=r"((r)[8]),"=r"((r)[9]),"=r"((r)[10]),"=r"((r)[11]), \
      "=r"((r)[12]),"=r"((r)[13]),"=r"((r)[14]),"=r"((r)[15]), \
      "=r"((r)[16]),"=r"((r)[17]),"=r"((r)[18]),"=r"((r)[19]), \
      "=r"((r)[20]),"=r"((r)[21]),"=r"((r)[22]),"=r"((r)[23]), \
      "=r"((r)[24]),"=r"((r)[25]),"=r"((r)[26]),"=r"((r)[27]), \
      "=r"((r)[28]),"=r"((r)[29]),"=r"((r)[30]),"=r"((r)[31]) \
    : "r"(ta))

#define TC_ST_X32(ta, r) asm volatile( \
    "tcgen05.st.sync.aligned.32x32b.x32.b32 [%0], " \
    "{%1,%2,%3,%4,%5,%6,%7,%8,%9,%10,%11,%12,%13,%14,%15,%16," \
    "%17,%18,%19,%20,%21,%22,%23,%24,%25,%26,%27,%28,%29,%30,%31,%32};" \
    :: "r"(ta), \
       "r"((r)[0]),"r"((r)[1]),"r"((r)[2]),"r"((r)[3]), \
       "r"((r)[4]),"r"((r)[5]),"r"((r)[6]),"r"((r)[7]), \
       "r"((r)[8]),"r"((r)[9]),"r"((r)[10]),"r"((r)[11]), \
       "r"((r)[12]),"r"((r)[13]),"r"((r)[14]),"r"((r)[15]), \
       "r"((r)[16]),"r"((r)[17]),"r"((r)[18]),"r"((r)[19]), \
       "r"((r)[20]),"r"((r)[21]),"r"((r)[22]),"r"((r)[23]), \
       "r"((r)[24]),"r"((r)[25]),"r"((r)[26]),"r"((r)[27]), \
       "r"((r)[28]),"r"((r)[29]),"r"((r)[30]),"r"((r)[31]) \
    : "memory")

#if ATTN_TCGEN
__device__ __forceinline__ void mma_bf16_ss(uint32_t d, uint64_t a, uint64_t b,
                                            uint32_t idesc, bool en) {
    uint32_t e = en ? 1u : 0u;
    asm volatile(
        "{\n\t.reg .pred p;\n\tsetp.ne.u32 p, %5, 0;\n\t"
        "tcgen05.mma.cta_group::1.kind::f16 [%0], %1, %2, %3, {%4,%4,%4,%4}, p;\n\t}"
        :: "r"(d), "l"(a), "l"(b), "r"(idesc), "r"(0u), "r"(e) : "memory");
}
// TS form: A in TMEM (per test_mma.cu / TCGEN05_MMA_F16).
__device__ __forceinline__ void mma_bf16_ts(uint32_t d, uint32_t a_tmem, uint64_t b,
                                            uint32_t idesc, bool en) {
    uint32_t e = en ? 1u : 0u;
    asm volatile(
        "{\n\t.reg .pred p;\n\tsetp.ne.u32 p, %5, 0;\n\t"
        "tcgen05.mma.cta_group::1.kind::f16 [%0], [%1], %2, %3, {%4,%4,%4,%4}, p;\n\t}"
        :: "r"(d), "r"(a_tmem), "l"(b), "r"(idesc), "r"(0u), "r"(e) : "memory");
}
#endif

// SMEM desc: SW128, version=1(Blackwell), SBO=64, LBO=1
static __device__ __forceinline__ uint64_t make_desc(uint32_t addr) {
    const uint64_t base = (uint64_t(2) << 61) | (uint64_t(1) << 46) |
                          (uint64_t(64) << 32) | (uint64_t(1) << 16);
    return base | ((uint64_t)(addr >> 4) & 0x3FFF);
}

// idesc kind::f16 bf16: dtype=F32(1<<4), atype=BF16(1<<7), btype=BF16(1<<10),
// N=64 ((64/8)<<17), M=128 ((128/16)<<24)
#define IDESC_BF16 ((1u<<4) | (1u<<7) | (1u<<10) | (8u<<17) | (8u<<24))

__device__ __forceinline__ uint32_t swz(uint32_t off) {
    return off ^ ((off >> 3) & 0x70);
}

#if ATTN_TCGEN
// 3-pass split GEMM (SS): (Ahi,Bhi) + (Ahi,Blo) + (Alo,Bhi). 12 dispatches.
__device__ __forceinline__ void issue_3pass(uint32_t dst, uint64_t ahi, uint64_t alo,
                                            uint64_t bhi, uint64_t blo, bool accum)
{
    #pragma unroll
    for (int p = 0; p < 3; p++) {
        uint64_t A = (p == 2) ? alo : ahi;
        uint64_t B = (p == 1) ? blo : bhi;
        #pragma unroll
        for (int s = 0; s < 4; s++)
            mma_bf16_ss(dst, A + s * 2, B + s * 2, IDESC_BF16,
                        accum || !(p == 0 && s == 0));
    }
}
// 3-pass split GEMM (TS): A hi at qa, A lo at qa+32 (TMEM cols). K=64 = 4
// steps; A advances 8 cols per K=16 step (test_mma_iter convention).
__device__ __forceinline__ void issue_3pass_ts(uint32_t dst, uint32_t qa,
                                               uint64_t bhi, uint64_t blo)
{
    #pragma unroll
    for (int p = 0; p < 3; p++) {
        uint32_t A = (p == 2) ? (qa + 32) : qa;
        uint64_t B = (p == 1) ? blo : bhi;
        #pragma unroll
        for (int s = 0; s < 4; s++)
            mma_bf16_ts(dst, A + s * 8, B + s * 2, IDESC_BF16,
                        !(p == 0 && s == 0));
    }
}

// Load W [64xK=64] fp32 -> bf16 hi/lo SW128 tile. 128 threads.
__device__ __forceinline__ void load_w_tile(char* smem, uint32_t hi_off,
                                            uint32_t lo_off, const float* W,
                                            int tid)
{
    #pragma unroll 4
    for (int j = 0; j < 8; j++) {
        int u = tid + j * 128;              // 0..1023 float4 units
        int d = u >> 4, e4 = (u & 15) * 4;
        float4 v = *(const float4*)(W + d * 64 + e4);
        __nv_bfloat16 h0 = __float2bfloat16(v.x), h1 = __float2bfloat16(v.y);
        __nv_bfloat16 h2 = __float2bfloat16(v.z), h3 = __float2bfloat16(v.w);
        __nv_bfloat162 hp0, hp1, lp0, lp1;
        hp0.x = h0; hp0.y = h1; hp1.x = h2; hp1.y = h3;
        lp0.x = __float2bfloat16(v.x - __bfloat162float(h0));
        lp0.y = __float2bfloat16(v.y - __bfloat162float(h1));
        lp1.x = __float2bfloat16(v.z - __bfloat162float(h2));
        lp1.y = __float2bfloat16(v.w - __bfloat162float(h3));
        uint2 hp, lp;
        hp.x = *(uint32_t*)&hp0; hp.y = *(uint32_t*)&hp1;
        lp.x = *(uint32_t*)&lp0; lp.y = *(uint32_t*)&lp1;
        uint32_t off = swz((uint32_t)(d * 128 + e4 * 2));
        *(uint2*)(smem + hi_off + off) = hp;
        *(uint2*)(smem + lo_off + off) = lp;
    }
}
#endif

// ============================================================================
// Kernel 1: tensor-core projection, 4 CTAs/SM (391.5us cfg, unchanged).
// ============================================================================
#define PX_HI  0
#define PX_LO  16384
#define PW_HI  32768
#define PW_LO  40960
#define PCTRL  49152
#define PSTG   0
#define PSTG_PITCH 528
#define P_TOTAL (PCTRL + 128)

__global__ void __launch_bounds__(128, 4) proj_tc_kernel(
    const float* __restrict__ qin, const float* __restrict__ kin,
    const float* __restrict__ vin, const float* __restrict__ Wq,
    const float* __restrict__ Wk, const float* __restrict__ Wv)
{
    extern __shared__ char smem[];
    const int tid = threadIdx.x;
    const int bx = blockIdx.x, n = blockIdx.y, w = blockIdx.z;
    const float* in; const float* W;
    if (w == 0)      { in = qin; W = Wq; }
    else if (w == 1) { in = kin; W = Wk; }
    else             { in = vin; W = Wv; }
    const bool fmaj = (w < 2);
    const int fb = bx;
    const int fb16 = bx >> 3, tb = bx & 7;

#if ATTN_TCGEN
    const uint32_t sb = smem_u32(smem);
    const int wid = tid >> 5;

    if (wid == 0) {
        TC_ALLOC(sb + PCTRL, 128);
        TC_RELINQ();
    }
    if (tid == 0) MBAR_INIT(sb + PCTRL + 8, 1);
    __syncthreads();
    uint32_t tmem;
    asm volatile("ld.shared.b32 %0, [%1];" : "=r"(tmem) : "r"(sb + PCTRL));
    const uint32_t mb = sb + PCTRL + 8;

    #pragma unroll 4
    for (int j = 0; j < 16; j++) {
        int u = tid + j * 128;
        int r = u >> 4, e4 = (u & 15) * 4;
        int t, f;
        if (fmaj) { t = r & 63;            f = fb * 2 + (r >> 6); }
        else      { t = tb * 8 + (r >> 4); f = fb16 * 16 + (r & 15); }
        float4 v = *(const float4*)(in + (((size_t)n * 64 + t) * 512 + f) * 64 + e4);
        __nv_bfloat16 h0 = __float2bfloat16(v.x), h1 = __float2bfloat16(v.y);
        __nv_bfloat16 h2 = __float2bfloat16(v.z), h3 = __float2bfloat16(v.w);
        __nv_bfloat162 hp0, hp1, lp0, lp1;
        hp0.x = h0; hp0.y = h1; hp1.x = h2; hp1.y = h3;
        lp0.x = __float2bfloat16(v.x - __bfloat162float(h0));
        lp0.y = __float2bfloat16(v.y - __bfloat162float(h1));
        lp1.x = __float2bfloat16(v.z - __bfloat162float(h2));
        lp1.y = __float2bfloat16(v.w - __bfloat162float(h3));
        uint2 hp, lp;
        hp.x = *(uint32_t*)&hp0; hp.y = *(uint32_t*)&hp1;
        lp.x = *(uint32_t*)&lp0; lp.y = *(uint32_t*)&lp1;
        uint32_t off = swz((uint32_t)(r * 128 + e4 * 2));
        *(uint2*)(smem + PX_HI + off) = hp;
        *(uint2*)(smem + PX_LO + off) = lp;
    }
    load_w_tile(smem, PW_HI, PW_LO, W, tid);
    FENCE_ASYNC();
    TC_FENCE_BEFORE();
    __syncthreads();

    if (wid == 0) {
        TC_FENCE_AFTER();
        if (elect_one()) {
            issue_3pass(tmem, make_desc(sb + PX_HI), make_desc(sb + PX_LO),
                        make_desc(sb + PW_HI), make_desc(sb + PW_LO), false);
            TC_COMMIT(mb);
        }
    }
    MBAR_WAIT(mb, 0);
    TC_FENCE_AFTER();

    {
        char* stg = smem + PSTG;
        #pragma unroll
        for (int cc = 0; cc < 64; cc += 32) {
            uint32_t sreg[32];
            TC_LD_X32(sreg, tmem + cc);
            TC_WAIT_LD();
            #pragma unroll
            for (int d = 0; d < 32; d++) {
                float v = __uint_as_float(sreg[d]);
                __nv_bfloat16 hb = __float2bfloat16(v);
                __nv_bfloat16 lb = __float2bfloat16(v - __bfloat162float(hb));
                uint32_t pk = ((uint32_t)(*(uint16_t*)&hb) << 16)
                            | (uint32_t)(*(uint16_t*)&lb);
                *(uint32_t*)(stg + (cc + d) * PSTG_PITCH + tid * 4) = pk;
            }
        }
    }
    TC_FENCE_BEFORE();
    __syncthreads();

    if (fmaj) {
        __nv_bfloat16* ohi = (w == 0) ? g_Qhi : g_Khi;
        __nv_bfloat16* olo = (w == 0) ? g_Qlo : g_Klo;
        #pragma unroll
        for (int j = 0; j < 8; j++) {
            int u = tid + j * 128;
            int rrow = u >> 3, seg = u & 7;
            int d = rrow >> 1, fl = rrow & 1;
            const char* src = smem + PSTG + d * PSTG_PITCH + fl * 256 + seg * 32;
            uint4 a = *(const uint4*)(src);
            uint4 b = *(const uint4*)(src + 16);
            uint4 hp, lp;
            hp.x = (a.y & 0xFFFF0000u) | (a.x >> 16);
            hp.y = (a.w & 0xFFFF0000u) | (a.z >> 16);
            hp.z = (b.y & 0xFFFF0000u) | (b.x >> 16);
            hp.w = (b.w & 0xFFFF0000u) | (b.z >> 16);
            lp.x = (a.y << 16) | (a.x & 0xFFFFu);
            lp.y = (a.w << 16) | (a.z & 0xFFFFu);
            lp.z = (b.y << 16) | (b.x & 0xFFFFu);
            lp.w = (b.w << 16) | (b.z & 0xFFFFu);
            size_t gbase = (((size_t)n * 64 + d) * 512 + fb * 2 + fl) * 64
                         + seg * 8;
            *(uint4*)(ohi + gbase) = hp;
            *(uint4*)(olo + gbase) = lp;
        }
    } else {
        #pragma unroll
        for (int q = 0; q < 4; q++) {
            int u2 = tid + q * 128;
            int e = u2 >> 3, tl = u2 & 7;
            const char* src = smem + PSTG + e * PSTG_PITCH + tl * 64;
            uint4 a = *(const uint4*)(src);
            uint4 b = *(const uint4*)(src + 16);
            uint4 c = *(const uint4*)(src + 32);
            uint4 d4 = *(const uint4*)(src + 48);
            uint4 h1, h2v, l1, l2v;
            h1.x = (a.y & 0xFFFF0000u) | (a.x >> 16);
            h1.y = (a.w & 0xFFFF0000u) | (a.z >> 16);
            h1.z = (b.y & 0xFFFF0000u) | (b.x >> 16);
            h1.w = (b.w & 0xFFFF0000u) | (b.z >> 16);
            h2v.x = (c.y & 0xFFFF0000u) | (c.x >> 16);
            h2v.y = (c.w & 0xFFFF0000u) | (c.z >> 16);
            h2v.z = (d4.y & 0xFFFF0000u) | (d4.x >> 16);
            h2v.w = (d4.w & 0xFFFF0000u) | (d4.z >> 16);
            l1.x = (a.y << 16) | (a.x & 0xFFFFu);
            l1.y = (a.w << 16) | (a.z & 0xFFFFu);
            l1.z = (b.y << 16) | (b.x & 0xFFFFu);
            l1.w = (b.w << 16) | (b.z & 0xFFFFu);
            l2v.x = (c.y << 16) | (c.x & 0xFFFFu);
            l2v.y = (c.w << 16) | (c.z & 0xFFFFu);
            l2v.z = (d4.y << 16) | (d4.x & 0xFFFFu);
            l2v.w = (d4.w << 16) | (d4.z & 0xFFFFu);
            size_t ga = ((size_t)(n * 64 + e)) * (64 * 512)
                      + (size_t)(tb * 8 + tl) * 512 + fb16 * 16;
            *(uint4*)(g_Vthi + ga) = h1;
            *(uint4*)(g_Vthi + ga + 8) = h2v;
            *(uint4*)(g_Vtlo + ga) = l1;
            *(uint4*)(g_Vtlo + ga + 8) = l2v;
        }
    }
    __syncthreads();
    if (wid == 0) TC_DEALLOC(tmem, 128);

#else   // ---------------- scalar fallback (non-'a' target) -----------------
    __shared__ float sWf[64 * 64];
    for (int i = tid; i < 4096; i += 128) sWf[i] = W[i];
    __syncthreads();
    for (int idx = tid; idx < 128 * 64; idx += 128) {
        int r = idx >> 6, d = idx & 63;
        int t, f;
        if (fmaj) { t = r & 63;            f = fb * 2 + (r >> 6); }
        else      { t = tb * 8 + (r >> 4); f = fb16 * 16 + (r & 15); }
        const float* xp = in + (((size_t)n * 64 + t) * 512 + f) * 64;
        float s = 0.0f;
        for (int e = 0; e < 64; e++) s = fmaf(xp[e], sWf[d * 64 + e], s);
        __nv_bfloat16 hb = __float2bfloat16(s);
        __nv_bfloat16 lb = __float2bfloat16(s - __bfloat162float(hb));
        if (fmaj) {
            size_t off = (((size_t)n * 64 + d) * 512 + f) * 64 + t;
            if (w == 0) { g_Qhi[off] = hb; g_Qlo[off] = lb; }
            else        { g_Khi[off] = hb; g_Klo[off] = lb; }
        } else {
            size_t off = ((size_t)(n * 64 + d)) * (64 * 512)
                       + (size_t)t * 512 + f;
            g_Vthi[off] = hb; g_Vtlo[off] = lb;
        }
    }
#endif
}

// ============================================================================
// Kernel 2: attention. Q lives in TMEM (TS-mode GEMM1) -> smem freed for V
// double-buffering (V(kc+1) prefetched with K(kc+1); no exposed V load).
// smem 98.4KB -> 2 CTAs/SM; TMEM 256/CTA: Q 0-63 | S0 64-127 | S1 128-191 |
// O 192-255. grid (4 qtile, 64 e, 8 n), block 256.
// ============================================================================
#define SM_PHI  0          // 16KB
#define SM_PLO  16384      // 16KB
#define SM_K    32768      // 2 bufs x {hi 8KB, lo 8KB}
#define SM_V    65536      // 2 bufs x {hi 8KB, lo 8KB}
#define SM_CTRL 98304      // +0 tmem ptr, +8 mbS0, +16 mbS1, +24 mb2
#define SM_RED  SM_PHI     // alias: reduction buffer (P dead post-loop)
#define SM_TOTAL (SM_CTRL + 128)   // 98432

#if ATTN_TCGEN
__device__ __forceinline__ void load_k_chunk(
    char* smem, const __nv_bfloat16* Khg, const __nv_bfloat16* Klg,
    int c, int b, int tid)
{
    const __nv_bfloat16* kh = Khg + c * 64 * 64;
    const __nv_bfloat16* kl = Klg + c * 64 * 64;
    char* kbase = smem + SM_K + b * 16384;
    #pragma unroll
    for (int j = 0; j < 2; j++) {
        int idx = tid + j * 256;            // 0..511 16B units
        int r = idx >> 3, c16 = idx & 7;
        uint32_t sw = swz((uint32_t)(r * 128 + c16 * 16));
        uint4 a  = *(const uint4*)(kh + r * 64 + c16 * 8);
        uint4 bb = *(const uint4*)(kl + r * 64 + c16 * 8);
        *(uint4*)(kbase + sw) = a;
        *(uint4*)(kbase + 8192 + sw) = bb;
    }
}

__device__ __forceinline__ void load_v_chunk(
    char* smem, const __nv_bfloat16* Vhg, const __nv_bfloat16* Vlg,
    int c, int b, int tid)
{
    char* vbase = smem + SM_V + b * 16384;
    #pragma unroll
    for (int j = 0; j < 2; j++) {
        int idx = tid + j * 256;
        int r = idx >> 3, c16 = idx & 7;
        uint32_t sw = swz((uint32_t)(r * 128 + c16 * 16));
        uint4 vh = *(const uint4*)(Vhg + (size_t)r * 512 + c * 64 + c16 * 8);
        uint4 vl = *(const uint4*)(Vlg + (size_t)r * 512 + c * 64 + c16 * 8);
        *(uint4*)(vbase + sw) = vh;
        *(uint4*)(vbase + 8192 + sw) = vl;
    }
}
#endif

__global__ void __launch_bounds__(256, 2) attn_tc_kernel()
{
    extern __shared__ char smem[];
    const int tid = threadIdx.x;
    const int qb = blockIdx.x, e = blockIdx.y, n = blockIdx.z;
    const size_t plane = (size_t)(n * 64 + e);
    const size_t qk_base = plane * 512 * 64;
    const __nv_bfloat16* Qhg = g_Qhi + qk_base + (size_t)qb * 128 * 64;
    const __nv_bfloat16* Qlg = g_Qlo + qk_base + (size_t)qb * 128 * 64;
    const __nv_bfloat16* Khg = g_Khi + qk_base;
    const __nv_bfloat16* Klg = g_Klo + qk_base;
    const __nv_bfloat16* Vhg = g_Vthi + plane * 64 * 512;
    const __nv_bfloat16* Vlg = g_Vtlo + plane * 64 * 512;

#if ATTN_TCGEN
    const uint32_t sb = smem_u32(smem);
    const int wid = tid >> 5, lid = tid & 31;
    const int row = (wid & 3) * 32 + lid;
    const int cb  = (wid >> 2) * 32;

    if (wid == 0) {
        TC_ALLOC(sb + SM_CTRL, 256);
        TC_RELINQ();
    }
    if (tid == 0) {
        MBAR_INIT(sb + SM_CTRL + 8, 1);
        MBAR_INIT(sb + SM_CTRL + 16, 1);
        MBAR_INIT(sb + SM_CTRL + 24, 1);
    }
    __syncthreads();
    uint32_t tmem;
    asm volatile("ld.shared.b32 %0, [%1];" : "=r"(tmem) : "r"(sb + SM_CTRL));
    const uint32_t tQA = tmem;           // Q: hi cols 0-31, lo cols 32-63
    uint32_t tS[2]; tS[0] = tmem + 64; tS[1] = tmem + 128;
    uint32_t mbS[2]; mbS[0] = sb + SM_CTRL + 8; mbS[1] = sb + SM_CTRL + 16;
    const uint32_t mb2 = sb + SM_CTRL + 24;
    const uint32_t tO = tmem + 192;

    // Prologue: warps 0-3 store their Q row (hi+lo) into TMEM; all threads
    // load K/V chunk 0.
    if (tid < 128) {
        uint32_t qh[32], ql[32];
        const uint4* ph = (const uint4*)(Qhg + (size_t)tid * 64);
        const uint4* pl = (const uint4*)(Qlg + (size_t)tid * 64);
        #pragma unroll
        for (int j = 0; j < 8; j++) {
            uint4 a = ph[j];
            qh[j * 4 + 0] = a.x; qh[j * 4 + 1] = a.y;
            qh[j * 4 + 2] = a.z; qh[j * 4 + 3] = a.w;
            uint4 b = pl[j];
            ql[j * 4 + 0] = b.x; ql[j * 4 + 1] = b.y;
            ql[j * 4 + 2] = b.z; ql[j * 4 + 3] = b.w;
        }
        const uint32_t woff = (uint32_t)(tid >> 5) << 21;
        TC_ST_X32(tQA + woff, qh);
        TC_ST_X32(tQA + 32 + woff, ql);
        TC_WAIT_ST();
    }
    load_k_chunk(smem, Khg, Klg, 0, 0, tid);
    load_v_chunk(smem, Vhg, Vlg, 0, 0, tid);
    FENCE_ASYNC();
    TC_FENCE_BEFORE();
    __syncthreads();

    const uint64_t dPh = make_desc(sb + SM_PHI), dPl = make_desc(sb + SM_PLO);
    uint64_t dKh[2], dKl[2], dVh[2], dVl[2];
    #pragma unroll
    for (int b = 0; b < 2; b++) {
        dKh[b] = make_desc(sb + SM_K + b * 16384);
        dKl[b] = make_desc(sb + SM_K + b * 16384 + 8192);
        dVh[b] = make_desc(sb + SM_V + b * 16384);
        dVl[b] = make_desc(sb + SM_V + b * 16384 + 8192);
    }

    // GEMM1(0) TS -> S0
    if (wid == 0) {
        TC_FENCE_AFTER();
        if (elect_one()) {
            issue_3pass_ts(tS[0], tQA, dKh[0], dKl[0]);
            TC_COMMIT(mbS[0]);
        }
    }

    float l_part = 0.0f;
    uint32_t sreg[32];

    for (int kc = 0; kc < 8; kc++) {
        // GEMM2(kc-1) done -> frees P tile and V buf (kc+1)&1
        if (kc > 0) MBAR_WAIT(mb2, (kc - 1) & 1);
        if (kc < 7) {
            load_k_chunk(smem, Khg, Klg, kc + 1, (kc + 1) & 1, tid);
            load_v_chunk(smem, Vhg, Vlg, kc + 1, (kc + 1) & 1, tid);
            FENCE_ASYNC();
        }
        __syncthreads();
        // GEMM1(kc+1) TS -> overlaps softmax(kc)
        if (kc < 7 && wid == 0) {
            TC_FENCE_AFTER();
            if (elect_one()) {
                issue_3pass_ts(tS[(kc + 1) & 1], tQA,
                               dKh[(kc + 1) & 1], dKl[(kc + 1) & 1]);
                TC_COMMIT(mbS[(kc + 1) & 1]);
            }
        }

        // S(kc) ready
        MBAR_WAIT(mbS[kc & 1], (kc >> 1) & 1);
        TC_FENCE_AFTER();
        TC_LD_X32(sreg, tS[kc & 1] + cb);
        TC_WAIT_LD();

        float l_loc = 0.0f;
        #pragma unroll
        for (int c = 0; c < 32; c++) {
            float sv = __uint_as_float(sreg[c]);
            float pe = __expf(sv * 0.125f);
            sreg[c] = __float_as_uint(pe);
            l_loc += pe;
        }
        l_part += l_loc;

        #pragma unroll
        for (int g = 0; g < 4; g++) {
            uint32_t hw[4], lw[4];
            #pragma unroll
            for (int x = 0; x < 4; x++) {
                float p0 = __uint_as_float(sreg[g * 8 + x * 2]);
                float p1 = __uint_as_float(sreg[g * 8 + x * 2 + 1]);
                uint32_t hi;
                asm("cvt.rn.bf16x2.f32 %0, %1, %2;" : "=r"(hi) : "f"(p1), "f"(p0));
                float hf0 = __uint_as_float(hi << 16);
                float hf1 = __uint_as_float(hi & 0xFFFF0000u);
                uint32_t lo;
                asm("cvt.rn.bf16x2.f32 %0, %1, %2;"
                    : "=r"(lo) : "f"(p1 - hf1), "f"(p0 - hf0));
                hw[x] = hi; lw[x] = lo;
            }
            uint32_t sw = swz((uint32_t)(row * 128 + cb * 2 + g * 16));
            *(uint4*)(smem + SM_PHI + sw) = make_uint4(hw[0], hw[1], hw[2], hw[3]);
            *(uint4*)(smem + SM_PLO + sw) = make_uint4(lw[0], lw[1], lw[2], lw[3]);
        }
        TC_FENCE_BEFORE();
        FENCE_ASYNC();
        __syncthreads();

        // GEMM2(kc) SS: O += P * V[kc&1]
        if (wid == 0) {
            TC_FENCE_AFTER();
            if (elect_one()) {
                issue_3pass(tO, dPh, dPl, dVh[kc & 1], dVl[kc & 1], kc > 0);
                TC_COMMIT(mb2);
            }
        }
    }

    MBAR_WAIT(mb2, 1);   // 8th GEMM2 commit => phase 7, parity 1
    TC_FENCE_AFTER();

    *(float*)(smem + SM_RED + tid * 4) = l_part;
    TC_LD_X32(sreg, tO + cb);
    TC_WAIT_LD();
    TC_FENCE_BEFORE();
    __syncthreads();
    const float l_sum = l_part + *(float*)(smem + SM_RED + (tid ^ 128) * 4);

    const float inv = 1.0f / l_sum;
    float* Og = g_Op + plane * 512 * 64 + (size_t)qb * 128 * 64
              + (size_t)row * 64 + cb;
    #pragma unroll
    for (int c4 = 0; c4 < 32; c4 += 4) {
        float4 ov = make_float4(__uint_as_float(sreg[c4 + 0]) * inv,
                                __uint_as_float(sreg[c4 + 1]) * inv,
                                __uint_as_float(sreg[c4 + 2]) * inv,
                                __uint_as_float(sreg[c4 + 3]) * inv);
        *(float4*)(Og + c4) = ov;
    }

    __syncthreads();
    if (wid == 0) TC_DEALLOC(tmem, 256);

#else   // ---------------- scalar fallback (non-'a' target) -----------------
    float* sK = (float*)smem;
    float* sV = sK + 64 * 65;

    float qreg[64];
    if (tid < 128) {
        #pragma unroll
        for (int t = 0; t < 64; t++)
            qreg[t] = __bfloat162float(Qhg[tid * 64 + t]) +
                      __bfloat162float(Qlg[tid * 64 + t]);
    }

    float o[64];
    #pragma unroll
    for (int t = 0; t < 64; t++) o[t] = 0.0f;
    float l_sum = 0.0f;

    for (int kc = 0; kc < 8; kc++) {
        __syncthreads();
        for (int i = tid; i < 4096; i += 256) {
            int r = i >> 6, c = i & 63;
            sK[r * 65 + c] = __bfloat162float(Khg[(size_t)(kc * 64 + r) * 64 + c]) +
                             __bfloat162float(Klg[(size_t)(kc * 64 + r) * 64 + c]);
            sV[r * 65 + c] = __bfloat162float(Vhg[(size_t)c * 512 + kc * 64 + r]) +
                             __bfloat162float(Vlg[(size_t)c * 512 + kc * 64 + r]);
        }
        __syncthreads();

        if (tid < 128) {
            for (int k = 0; k < 64; k++) {
                float s = 0.0f;
                #pragma unroll 16
                for (int t = 0; t < 64; t++) s = fmaf(qreg[t], sK[k * 65 + t], s);
                float p = __expf(s * 0.125f);
                l_sum += p;
                #pragma unroll 16
                for (int t = 0; t < 64; t++) o[t] = fmaf(p, sV[k * 65 + t], o[t]);
            }
        }
    }

    if (tid < 128) {
        const float inv = 1.0f / l_sum;
        float* Og = g_Op + plane * 512 * 64 + (size_t)qb * 128 * 64
                  + (size_t)tid * 64;
        #pragma unroll
        for (int c = 0; c < 64; c++) Og[c] = o[c] * inv;
    }
#endif
}

// ============================================================================
// Kernel 3: tensor-core output projection (391.5us cfg, unchanged).
// ============================================================================
#define OSTG   0
#define OSTG_PITCH 68
#define OX_HI  17408
#define OX_LO  33792
#define OW_HI  50176
#define OW_LO  58368
#define OB_    66560
#define OCTRL  66816
#define O_TOTAL (OCTRL + 128)

__global__ void __launch_bounds__(128, 3) out_tc_kernel(
    const float* __restrict__ Wo, const float* __restrict__ bo,
    float* __restrict__ out)
{
    extern __shared__ char smem[];
    const int tid = threadIdx.x;
    const int qp = blockIdx.x, n = blockIdx.y;

#if ATTN_TCGEN
    const uint32_t sb = smem_u32(smem);
    const int wid = tid >> 5;

    if (wid == 0) {
        TC_ALLOC(sb + OCTRL, 128);
        TC_RELINQ();
    }
    if (tid == 0) MBAR_INIT(sb + OCTRL + 8, 1);
    if (tid < 64) *(float*)(smem + OB_ + tid * 4) = bo[tid];
    __syncthreads();
    uint32_t tmem;
    asm volatile("ld.shared.b32 %0, [%1];" : "=r"(tmem) : "r"(sb + OCTRL));
    const uint32_t mb = sb + OCTRL + 8;

    load_w_tile(smem, OW_HI, OW_LO, Wo, tid);

    float* stg = (float*)(smem + OSTG);
    #pragma unroll
    for (int qi = 0; qi < 2; qi++) {
        const int q = qp * 2 + qi;
        if (qi == 1) __syncthreads();
        #pragma unroll 4
        for (int j = 0; j < 8; j++) {
            int u = tid + j * 128;
            int e = u >> 4, t4 = (u & 15) * 4;
            float4 v = *(const float4*)(g_Op +
                (((size_t)n * 64 + e) * 512 + q) * 64 + t4);
            float* d = &stg[e * OSTG_PITCH + t4];
            d[0] = v.x; d[1] = v.y; d[2] = v.z; d[3] = v.w;
        }
        __syncthreads();
        {
            const int t = tid & 63, eh = tid >> 6;
            const int r = qi * 64 + t;
            #pragma unroll
            for (int g = 0; g < 4; g++) {
                uint32_t hw[4], lw[4];
                #pragma unroll
                for (int x = 0; x < 4; x++) {
                    int e = eh * 32 + g * 8 + x * 2;
                    float v0 = stg[e * OSTG_PITCH + t];
                    float v1 = stg[(e + 1) * OSTG_PITCH + t];
                    uint32_t hi;
                    asm("cvt.rn.bf16x2.f32 %0, %1, %2;"
                        : "=r"(hi) : "f"(v1), "f"(v0));
                    float hf0 = __uint_as_float(hi << 16);
                    float hf1 = __uint_as_float(hi & 0xFFFF0000u);
                    uint32_t lo;
                    asm("cvt.rn.bf16x2.f32 %0, %1, %2;"
                        : "=r"(lo) : "f"(v1 - hf1), "f"(v0 - hf0));
                    hw[x] = hi; lw[x] = lo;
                }
                uint32_t sw = swz((uint32_t)(r * 128 + eh * 64 + g * 16));
                *(uint4*)(smem + OX_HI + sw) = make_uint4(hw[0], hw[1], hw[2], hw[3]);
                *(uint4*)(smem + OX_LO + sw) = make_uint4(lw[0], lw[1], lw[2], lw[3]);
            }
        }
    }
    FENCE_ASYNC();
    TC_FENCE_BEFORE();
    __syncthreads();

    if (wid == 0) {
        TC_FENCE_AFTER();
        if (elect_one()) {
            issue_3pass(tmem, make_desc(sb + OX_HI), make_desc(sb + OX_LO),
                        make_desc(sb + OW_HI), make_desc(sb + OW_LO), false);
            TC_COMMIT(mb);
        }
    }
    MBAR_WAIT(mb, 0);
    TC_FENCE_AFTER();

    {
        const int qi = tid >> 6, t = tid & 63;
        const int q = qp * 2 + qi;
        float* ob = out + (((size_t)n * 64 + t) * 512 + q) * 64;
        const float* sbias = (const float*)(smem + OB_);
        #pragma unroll
        for (int cc = 0; cc < 64; cc += 32) {
            uint32_t sreg[32];
            TC_LD_X32(sreg, tmem + cc);
            TC_WAIT_LD();
            #pragma unroll
            for (int d4 = 0; d4 < 32; d4 += 4) {
                float4 v = make_float4(
                    __uint_as_float(sreg[d4 + 0]) + sbias[cc + d4 + 0],
                    __uint_as_float(sreg[d4 + 1]) + sbias[cc + d4 + 1],
                    __uint_as_float(sreg[d4 + 2]) + sbias[cc + d4 + 2],
                    __uint_as_float(sreg[d4 + 3]) + sbias[cc + d4 + 3]);
                *(float4*)(ob + cc + d4) = v;
            }
        }
    }
    TC_FENCE_BEFORE();
    __syncthreads();
    if (wid == 0) TC_DEALLOC(tmem, 128);

#else   // ---------------- scalar fallback (non-'a' target) -----------------
    __shared__ float sWf[64 * 64];
    __shared__ float sbv[64];
    for (int i = tid; i < 4096; i += 128) sWf[i] = Wo[i];
    if (tid < 64) sbv[tid] = bo[tid];
    __syncthreads();
    for (int idx = tid; idx < 128 * 64; idx += 128) {
        int r = idx >> 6, d = idx & 63;
        int qi = r >> 6, t = r & 63;
        int q = qp * 2 + qi;
        float s = 0.0f;
        for (int e = 0; e < 64; e++)
            s = fmaf(g_Op[(((size_t)n * 64 + e) * 512 + q) * 64 + t],
                     sWf[d * 64 + e], s);
        out[(((size_t)n * 64 + t) * 512 + q) * 64 + d] = s + sbv[d];
    }
#endif
}

// ---------------------------------------------------------------------------
extern "C" void kernel_launch(void* const* d_in, const int* in_sizes, int n_in,
                              void* d_out, int out_size)
{
    const float* value = (const float*)d_in[0];
    const float* key   = (const float*)d_in[1];
    const float* query = (const float*)d_in[2];
    const float* Wv    = (const float*)d_in[3];
    const float* Wk    = (const float*)d_in[4];
    const float* Wq    = (const float*)d_in[5];
    const float* Wo    = (const float*)d_in[6];
    const float* bo    = (const float*)d_in[7];
    float* out = (float*)d_out;

    cudaFuncSetAttribute(proj_tc_kernel,
                         cudaFuncAttributeMaxDynamicSharedMemorySize, P_TOTAL);
    cudaFuncSetAttribute(attn_tc_kernel,
                         cudaFuncAttributeMaxDynamicSharedMemorySize, SM_TOTAL);
    cudaFuncSetAttribute(out_tc_kernel,
                         cudaFuncAttributeMaxDynamicSharedMemorySize, O_TOTAL);

    dim3 g1(256, 8, 3);
    proj_tc_kernel<<<g1, 128, P_TOTAL>>>(query, key, value, Wq, Wk, Wv);

    dim3 g2(4, 64, 8);
    attn_tc_kernel<<<g2, 256, SM_TOTAL>>>();

    dim3 g3(256, 8);
    out_tc_kernel<<<g3, 128, O_TOTAL>>>(Wo, bo, out);
}

// round 17
// speedup vs baseline: 1.2519x; 1.0501x over previous
#include <cuda_runtime.h>
#include <cuda_bf16.h>
#include <cstdint>
#include <math.h>

// Problem dims: N=8, T=64, F=512, E=64
#define PITCH 65

// Arch-feature gate: tcgen05 exists only on sm_100a/sm_103a ('a' targets).
#if defined(__CUDA_ARCH__) && (defined(__CUDA_ARCH_FEAT_SM103_ALL) || \
    defined(__CUDA_ARCH_FEAT_SM100_ALL) || \
    (defined(__CUDA_ARCH_SPECIFIC__) && (__CUDA_ARCH_SPECIFIC__ >= 1000)))
#define ATTN_TCGEN 1
#else
#define ATTN_TCGEN 0
#endif

#define NELEM (8u * 64u * 512u * 64u)
// Projected Q/K in bf16 hi/lo, layout [n][e][f][t]
__device__ __nv_bfloat16 g_Qhi[NELEM];
__device__ __nv_bfloat16 g_Qlo[NELEM];
__device__ __nv_bfloat16 g_Khi[NELEM];
__device__ __nv_bfloat16 g_Klo[NELEM];
// V transposed, bf16 hi/lo, layout [n][e][t][f] (written directly by proj_tc)
__device__ __nv_bfloat16 g_Vthi[NELEM];
__device__ __nv_bfloat16 g_Vtlo[NELEM];
// Attention output fp32 [n][e][q][t]
__device__ float g_Op[NELEM];

// ============================================================================
// PTX helpers
// ============================================================================
__device__ __forceinline__ uint32_t smem_u32(const void* p) {
    uint32_t a;
    asm("{ .reg .u64 t; cvta.to.shared.u64 t, %1; cvt.u32.u64 %0, t; }"
        : "=r"(a) : "l"(p));
    return a;
}
#if ATTN_TCGEN
__device__ __forceinline__ uint32_t elect_one() {
    uint32_t p;
    asm volatile("{\n\t.reg .pred p;\n\telect.sync _|p, 0xFFFFFFFF;\n\t"
                 "selp.b32 %0, 1, 0, p;\n\t}" : "=r"(p));
    return p;
}
#endif
#define MBAR_INIT(a, c) \
    asm volatile("mbarrier.init.shared.b64 [%0], %1;" :: "r"(a), "r"(c) : "memory")
#define MBAR_WAIT(a, ph) do { \
    uint32_t _m = (a), _p = (ph), _d; \
    asm volatile("{\n\t.reg .pred p;\n\t" \
        "mbarrier.try_wait.parity.acquire.cta.shared::cta.b64 p, [%1], %2;\n\t" \
        "selp.b32 %0, 1, 0, p;\n\t}" : "=r"(_d) : "r"(_m), "r"(_p) : "memory"); \
    if (!_d) { \
        asm volatile("{\n\t.reg .pred P1;\n\tWL_%=: \n\t" \
            "mbarrier.try_wait.parity.acquire.cta.shared::cta.b64 P1, [%0], %1, 0x989680;\n\t" \
            "@P1 bra.uni WD_%=;\n\tbra.uni WL_%=;\n\tWD_%=: \n\t}" \
            :: "r"(_m), "r"(_p) : "memory"); \
    } } while (0)

#define TC_ALLOC(sa, n)  asm volatile( \
    "tcgen05.alloc.cta_group::1.sync.aligned.shared::cta.b32 [%0], %1;" \
    :: "r"(sa), "r"(n) : "memory")
#define TC_DEALLOC(t, n) asm volatile( \
    "tcgen05.dealloc.cta_group::1.sync.aligned.b32 %0, %1;" :: "r"(t), "r"(n))
#define TC_RELINQ() asm volatile("tcgen05.relinquish_alloc_permit.cta_group::1.sync.aligned;")
#define TC_COMMIT(mb) asm volatile( \
    "tcgen05.commit.cta_group::1.mbarrier::arrive::one.shared::cluster.b64 [%0];" \
    :: "r"(mb) : "memory")
#define TC_WAIT_LD() asm volatile("tcgen05.wait::ld.sync.aligned;" ::: "memory")
#define TC_WAIT_ST() asm volatile("tcgen05.wait::st.sync.aligned;" ::: "memory")
#define TC_FENCE_BEFORE() asm volatile("tcgen05.fence::before_thread_sync;" ::: "memory")
#define TC_FENCE_AFTER()  asm volatile("tcgen05.fence::after_thread_sync;" ::: "memory")
#define FENCE_ASYNC() asm volatile("fence.proxy.async.shared::cta;" ::: "memory")

#define TC_LD_X32(r, ta) asm volatile( \
    "tcgen05.ld.sync.aligned.32x32b.x32.b32 " \
    "{%0,%1,%2,%3,%4,%5,%6,%7,%8,%9,%10,%11,%12,%13,%14,%15," \
    "%16,%17,%18,%19,%20,%21,%22,%23,%24,%25,%26,%27,%28,%29,%30,%31}, [%32];" \
    : "=r"((r)[0]),"=r"((r)[1]),"=r"((r)[2]),"=r"((r)[3]), \
      "=r"((r)[4]),"=r"((r)[5]),"=r"((r)[6]),"=r"((r)[7]), \
      "=r"((r)[8]),"=r"((r)[9]),"=r"((r)[10]),"=r"((r)[11]), \
      "=r"((r)[12]),"=r"((r)[13]),"=r"((r)[14]),"=r"((r)[15]), \
      "=r"((r)[16]),"=r"((r)[17]),"=r"((r)[18]),"=r"((r)[19]), \
      "=r"((r)[20]),"=r"((r)[21]),"=r"((r)[22]),"=r"((r)[23]), \
      "=r"((r)[24]),"=r"((r)[25]),"=r"((r)[26]),"=r"((r)[27]), \
      "=r"((r)[28]),"=r"((r)[29]),"=r"((r)[30]),"=r"((r)[31]) \
    : "r"(ta))

#define TC_ST_X32(ta, r) asm volatile( \
    "tcgen05.st.sync.aligned.32x32b.x32.b32 [%0], " \
    "{%1,%2,%3,%4,%5,%6,%7,%8,%9,%10,%11,%12,%13,%14,%15,%16," \
    "%17,%18,%19,%20,%21,%22,%23,%24,%25,%26,%27,%28,%29,%30,%31,%32};" \
    :: "r"(ta), \
       "r"((r)[0]),"r"((r)[1]),"r"((r)[2]),"r"((r)[3]), \
       "r"((r)[4]),"r"((r)[5]),"r"((r)[6]),"r"((r)[7]), \
       "r"((r)[8]),"r"((r)[9]),"r"((r)[10]),"r"((r)[11]), \
       "r"((r)[12]),"r"((r)[13]),"r"((r)[14]),"r"((r)[15]), \
       "r"((r)[16]),"r"((r)[17]),"r"((r)[18]),"r"((r)[19]), \
       "r"((r)[20]),"r"((r)[21]),"r"((r)[22]),"r"((r)[23]), \
       "r"((r)[24]),"r"((r)[25]),"r"((r)[26]),"r"((r)[27]), \
       "r"((r)[28]),"r"((r)[29]),"r"((r)[30]),"r"((r)[31]) \
    : "memory")

#if ATTN_TCGEN
__device__ __forceinline__ void mma_bf16_ss(uint32_t d, uint64_t a, uint64_t b,
                                            uint32_t idesc, bool en) {
    uint32_t e = en ? 1u : 0u;
    asm volatile(
        "{\n\t.reg .pred p;\n\tsetp.ne.u32 p, %5, 0;\n\t"
        "tcgen05.mma.cta_group::1.kind::f16 [%0], %1, %2, %3, {%4,%4,%4,%4}, p;\n\t}"
        :: "r"(d), "l"(a), "l"(b), "r"(idesc), "r"(0u), "r"(e) : "memory");
}
// TS form: A in TMEM (per test_mma.cu / TCGEN05_MMA_F16).
__device__ __forceinline__ void mma_bf16_ts(uint32_t d, uint32_t a_tmem, uint64_t b,
                                            uint32_t idesc, bool en) {
    uint32_t e = en ? 1u : 0u;
    asm volatile(
        "{\n\t.reg .pred p;\n\tsetp.ne.u32 p, %5, 0;\n\t"
        "tcgen05.mma.cta_group::1.kind::f16 [%0], [%1], %2, %3, {%4,%4,%4,%4}, p;\n\t}"
        :: "r"(d), "r"(a_tmem), "l"(b), "r"(idesc), "r"(0u), "r"(e) : "memory");
}
#endif

// SMEM desc: SW128, version=1(Blackwell), SBO=64, LBO=1
static __device__ __forceinline__ uint64_t make_desc(uint32_t addr) {
    const uint64_t base = (uint64_t(2) << 61) | (uint64_t(1) << 46) |
                          (uint64_t(64) << 32) | (uint64_t(1) << 16);
    return base | ((uint64_t)(addr >> 4) & 0x3FFF);
}

// idesc kind::f16 bf16: dtype=F32(1<<4), atype=BF16(1<<7), btype=BF16(1<<10),
// N=64 ((64/8)<<17), M=128 ((128/16)<<24)
#define IDESC_BF16 ((1u<<4) | (1u<<7) | (1u<<10) | (8u<<17) | (8u<<24))

__device__ __forceinline__ uint32_t swz(uint32_t off) {
    return off ^ ((off >> 3) & 0x70);
}

#if ATTN_TCGEN
// 3-pass split GEMM (SS): (Ahi,Bhi) + (Ahi,Blo) + (Alo,Bhi). 12 dispatches.
__device__ __forceinline__ void issue_3pass(uint32_t dst, uint64_t ahi, uint64_t alo,
                                            uint64_t bhi, uint64_t blo, bool accum)
{
    #pragma unroll
    for (int p = 0; p < 3; p++) {
        uint64_t A = (p == 2) ? alo : ahi;
        uint64_t B = (p == 1) ? blo : bhi;
        #pragma unroll
        for (int s = 0; s < 4; s++)
            mma_bf16_ss(dst, A + s * 2, B + s * 2, IDESC_BF16,
                        accum || !(p == 0 && s == 0));
    }
}
// 3-pass split GEMM (TS): A hi at qa, A lo at qa+32 (TMEM cols).
__device__ __forceinline__ void issue_3pass_ts(uint32_t dst, uint32_t qa,
                                               uint64_t bhi, uint64_t blo)
{
    #pragma unroll
    for (int p = 0; p < 3; p++) {
        uint32_t A = (p == 2) ? (qa + 32) : qa;
        uint64_t B = (p == 1) ? blo : bhi;
        #pragma unroll
        for (int s = 0; s < 4; s++)
            mma_bf16_ts(dst, A + s * 8, B + s * 2, IDESC_BF16,
                        !(p == 0 && s == 0));
    }
}

// Load W [64xK=64] fp32 -> bf16 hi/lo SW128 tile. 256 threads.
__device__ __forceinline__ void load_w_tile(char* smem, uint32_t hi_off,
                                            uint32_t lo_off, const float* W,
                                            int tid)
{
    #pragma unroll
    for (int j = 0; j < 4; j++) {
        int u = tid + j * 256;              // 0..1023 float4 units
        int d = u >> 4, e4 = (u & 15) * 4;
        float4 v = *(const float4*)(W + d * 64 + e4);
        __nv_bfloat16 h0 = __float2bfloat16(v.x), h1 = __float2bfloat16(v.y);
        __nv_bfloat16 h2 = __float2bfloat16(v.z), h3 = __float2bfloat16(v.w);
        __nv_bfloat162 hp0, hp1, lp0, lp1;
        hp0.x = h0; hp0.y = h1; hp1.x = h2; hp1.y = h3;
        lp0.x = __float2bfloat16(v.x - __bfloat162float(h0));
        lp0.y = __float2bfloat16(v.y - __bfloat162float(h1));
        lp1.x = __float2bfloat16(v.z - __bfloat162float(h2));
        lp1.y = __float2bfloat16(v.w - __bfloat162float(h3));
        uint2 hp, lp;
        hp.x = *(uint32_t*)&hp0; hp.y = *(uint32_t*)&hp1;
        lp.x = *(uint32_t*)&lp0; lp.y = *(uint32_t*)&lp1;
        uint32_t off = swz((uint32_t)(d * 128 + e4 * 2));
        *(uint2*)(smem + hi_off + off) = hp;
        *(uint2*)(smem + lo_off + off) = lp;
    }
}
#endif

// ============================================================================
// Kernel 1: tensor-core projection, 256 threads x 4 CTAs/SM (32 warps/SM).
// grid (256, 8, 3). Per CTA M=128 x K=64 x N=64, 3-pass bf16 MMA.
// Stage phase column-split across warp halves (1 TC_LD_X32/thread).
// ============================================================================
#define PX_HI  0
#define PX_LO  16384
#define PW_HI  32768
#define PW_LO  40960
#define PCTRL  49152
#define PSTG   0
#define PSTG_PITCH 528
#define P_TOTAL (PCTRL + 128)

__global__ void __launch_bounds__(256, 4) proj_tc_kernel(
    const float* __restrict__ qin, const float* __restrict__ kin,
    const float* __restrict__ vin, const float* __restrict__ Wq,
    const float* __restrict__ Wk, const float* __restrict__ Wv)
{
    extern __shared__ char smem[];
    const int tid = threadIdx.x;
    const int bx = blockIdx.x, n = blockIdx.y, w = blockIdx.z;
    const float* in; const float* W;
    if (w == 0)      { in = qin; W = Wq; }
    else if (w == 1) { in = kin; W = Wk; }
    else             { in = vin; W = Wv; }
    const bool fmaj = (w < 2);
    const int fb = bx;
    const int fb16 = bx >> 3, tb = bx & 7;

#if ATTN_TCGEN
    const uint32_t sb = smem_u32(smem);
    const int wid = tid >> 5, lid = tid & 31;

    if (wid == 0) {
        TC_ALLOC(sb + PCTRL, 128);
        TC_RELINQ();
    }
    if (tid == 0) MBAR_INIT(sb + PCTRL + 8, 1);
    __syncthreads();
    uint32_t tmem;
    asm volatile("ld.shared.b32 %0, [%1];" : "=r"(tmem) : "r"(sb + PCTRL));
    const uint32_t mb = sb + PCTRL + 8;

    // ---- Load X [128 rows x 64 e] fp32 -> bf16 hi/lo, 1 SW128 tile ----
    #pragma unroll
    for (int j = 0; j < 8; j++) {
        int u = tid + j * 256;              // 0..2047 float4 units
        int r = u >> 4, e4 = (u & 15) * 4;
        int t, f;
        if (fmaj) { t = r & 63;            f = fb * 2 + (r >> 6); }
        else      { t = tb * 8 + (r >> 4); f = fb16 * 16 + (r & 15); }
        float4 v = *(const float4*)(in + (((size_t)n * 64 + t) * 512 + f) * 64 + e4);
        __nv_bfloat16 h0 = __float2bfloat16(v.x), h1 = __float2bfloat16(v.y);
        __nv_bfloat16 h2 = __float2bfloat16(v.z), h3 = __float2bfloat16(v.w);
        __nv_bfloat162 hp0, hp1, lp0, lp1;
        hp0.x = h0; hp0.y = h1; hp1.x = h2; hp1.y = h3;
        lp0.x = __float2bfloat16(v.x - __bfloat162float(h0));
        lp0.y = __float2bfloat16(v.y - __bfloat162float(h1));
        lp1.x = __float2bfloat16(v.z - __bfloat162float(h2));
        lp1.y = __float2bfloat16(v.w - __bfloat162float(h3));
        uint2 hp, lp;
        hp.x = *(uint32_t*)&hp0; hp.y = *(uint32_t*)&hp1;
        lp.x = *(uint32_t*)&lp0; lp.y = *(uint32_t*)&lp1;
        uint32_t off = swz((uint32_t)(r * 128 + e4 * 2));
        *(uint2*)(smem + PX_HI + off) = hp;
        *(uint2*)(smem + PX_LO + off) = lp;
    }
    load_w_tile(smem, PW_HI, PW_LO, W, tid);
    FENCE_ASYNC();
    TC_FENCE_BEFORE();
    __syncthreads();

    if (wid == 0) {
        TC_FENCE_AFTER();
        if (elect_one()) {
            issue_3pass(tmem, make_desc(sb + PX_HI), make_desc(sb + PX_LO),
                        make_desc(sb + PW_HI), make_desc(sb + PW_LO), false);
            TC_COMMIT(mb);
        }
    }
    MBAR_WAIT(mb, 0);
    TC_FENCE_AFTER();

    // ---- Stage (column-split): warps 0-3 cols 0-31, warps 4-7 cols 32-63.
    // Pack (hi16<<16|lo16) at [d][row], pitch 528B (X/W smem dead). ----
    {
        char* stg = smem + PSTG;
        const int h = wid >> 2;
        const int rr = (wid & 3) * 32 + lid;   // TMEM lane / row
        uint32_t sreg[32];
        TC_LD_X32(sreg, tmem + h * 32);
        TC_WAIT_LD();
        #pragma unroll
        for (int d = 0; d < 32; d++) {
            float v = __uint_as_float(sreg[d]);
            __nv_bfloat16 hb = __float2bfloat16(v);
            __nv_bfloat16 lb = __float2bfloat16(v - __bfloat162float(hb));
            uint32_t pk = ((uint32_t)(*(uint16_t*)&hb) << 16)
                        | (uint32_t)(*(uint16_t*)&lb);
            *(uint32_t*)(stg + (h * 32 + d) * PSTG_PITCH + rr * 4) = pk;
        }
    }
    TC_FENCE_BEFORE();
    __syncthreads();

    if (fmaj) {
        __nv_bfloat16* ohi = (w == 0) ? g_Qhi : g_Khi;
        __nv_bfloat16* olo = (w == 0) ? g_Qlo : g_Klo;
        #pragma unroll
        for (int j = 0; j < 4; j++) {
            int u = tid + j * 256;              // 0..1023
            int rrow = u >> 3, seg = u & 7;
            int d = rrow >> 1, fl = rrow & 1;
            const char* src = smem + PSTG + d * PSTG_PITCH + fl * 256 + seg * 32;
            uint4 a = *(const uint4*)(src);
            uint4 b = *(const uint4*)(src + 16);
            uint4 hp, lp;
            hp.x = (a.y & 0xFFFF0000u) | (a.x >> 16);
            hp.y = (a.w & 0xFFFF0000u) | (a.z >> 16);
            hp.z = (b.y & 0xFFFF0000u) | (b.x >> 16);
            hp.w = (b.w & 0xFFFF0000u) | (b.z >> 16);
            lp.x = (a.y << 16) | (a.x & 0xFFFFu);
            lp.y = (a.w << 16) | (a.z & 0xFFFFu);
            lp.z = (b.y << 16) | (b.x & 0xFFFFu);
            lp.w = (b.w << 16) | (b.z & 0xFFFFu);
            size_t gbase = (((size_t)n * 64 + d) * 512 + fb * 2 + fl) * 64
                         + seg * 8;
            *(uint4*)(ohi + gbase) = hp;
            *(uint4*)(olo + gbase) = lp;
        }
    } else {
        #pragma unroll
        for (int q = 0; q < 2; q++) {
            int u2 = tid + q * 256;             // 0..511
            int e = u2 >> 3, tl = u2 & 7;
            const char* src = smem + PSTG + e * PSTG_PITCH + tl * 64;
            uint4 a = *(const uint4*)(src);
            uint4 b = *(const uint4*)(src + 16);
            uint4 c = *(const uint4*)(src + 32);
            uint4 d4 = *(const uint4*)(src + 48);
            uint4 h1, h2v, l1, l2v;
            h1.x = (a.y & 0xFFFF0000u) | (a.x >> 16);
            h1.y = (a.w & 0xFFFF0000u) | (a.z >> 16);
            h1.z = (b.y & 0xFFFF0000u) | (b.x >> 16);
            h1.w = (b.w & 0xFFFF0000u) | (b.z >> 16);
            h2v.x = (c.y & 0xFFFF0000u) | (c.x >> 16);
            h2v.y = (c.w & 0xFFFF0000u) | (c.z >> 16);
            h2v.z = (d4.y & 0xFFFF0000u) | (d4.x >> 16);
            h2v.w = (d4.w & 0xFFFF0000u) | (d4.z >> 16);
            l1.x = (a.y << 16) | (a.x & 0xFFFFu);
            l1.y = (a.w << 16) | (a.z & 0xFFFFu);
            l1.z = (b.y << 16) | (b.x & 0xFFFFu);
            l1.w = (b.w << 16) | (b.z & 0xFFFFu);
            l2v.x = (c.y << 16) | (c.x & 0xFFFFu);
            l2v.y = (c.w << 16) | (c.z & 0xFFFFu);
            l2v.z = (d4.y << 16) | (d4.x & 0xFFFFu);
            l2v.w = (d4.w << 16) | (d4.z & 0xFFFFu);
            size_t ga = ((size_t)(n * 64 + e)) * (64 * 512)
                      + (size_t)(tb * 8 + tl) * 512 + fb16 * 16;
            *(uint4*)(g_Vthi + ga) = h1;
            *(uint4*)(g_Vthi + ga + 8) = h2v;
            *(uint4*)(g_Vtlo + ga) = l1;
            *(uint4*)(g_Vtlo + ga + 8) = l2v;
        }
    }
    __syncthreads();
    if (wid == 0) TC_DEALLOC(tmem, 128);

#else   // ---------------- scalar fallback (non-'a' target) -----------------
    __shared__ float sWf[64 * 64];
    for (int i = tid; i < 4096; i += 256) sWf[i] = W[i];
    __syncthreads();
    for (int idx = tid; idx < 128 * 64; idx += 256) {
        int r = idx >> 6, d = idx & 63;
        int t, f;
        if (fmaj) { t = r & 63;            f = fb * 2 + (r >> 6); }
        else      { t = tb * 8 + (r >> 4); f = fb16 * 16 + (r & 15); }
        const float* xp = in + (((size_t)n * 64 + t) * 512 + f) * 64;
        float s = 0.0f;
        for (int e = 0; e < 64; e++) s = fmaf(xp[e], sWf[d * 64 + e], s);
        __nv_bfloat16 hb = __float2bfloat16(s);
        __nv_bfloat16 lb = __float2bfloat16(s - __bfloat162float(hb));
        if (fmaj) {
            size_t off = (((size_t)n * 64 + d) * 512 + f) * 64 + t;
            if (w == 0) { g_Qhi[off] = hb; g_Qlo[off] = lb; }
            else        { g_Khi[off] = hb; g_Klo[off] = lb; }
        } else {
            size_t off = ((size_t)(n * 64 + d)) * (64 * 512)
                       + (size_t)t * 512 + f;
            g_Vthi[off] = hb; g_Vtlo[off] = lb;
        }
    }
#endif
}

// ============================================================================
// Kernel 2: attention (374.9us cfg, unchanged). Q in TMEM, V double-buffered.
// ============================================================================
#define SM_PHI  0
#define SM_PLO  16384
#define SM_K    32768
#define SM_V    65536
#define SM_CTRL 98304
#define SM_RED  SM_PHI
#define SM_TOTAL (SM_CTRL + 128)

#if ATTN_TCGEN
__device__ __forceinline__ void load_k_chunk(
    char* smem, const __nv_bfloat16* Khg, const __nv_bfloat16* Klg,
    int c, int b, int tid)
{
    const __nv_bfloat16* kh = Khg + c * 64 * 64;
    const __nv_bfloat16* kl = Klg + c * 64 * 64;
    char* kbase = smem + SM_K + b * 16384;
    #pragma unroll
    for (int j = 0; j < 2; j++) {
        int idx = tid + j * 256;
        int r = idx >> 3, c16 = idx & 7;
        uint32_t sw = swz((uint32_t)(r * 128 + c16 * 16));
        uint4 a  = *(const uint4*)(kh + r * 64 + c16 * 8);
        uint4 bb = *(const uint4*)(kl + r * 64 + c16 * 8);
        *(uint4*)(kbase + sw) = a;
        *(uint4*)(kbase + 8192 + sw) = bb;
    }
}

__device__ __forceinline__ void load_v_chunk(
    char* smem, const __nv_bfloat16* Vhg, const __nv_bfloat16* Vlg,
    int c, int b, int tid)
{
    char* vbase = smem + SM_V + b * 16384;
    #pragma unroll
    for (int j = 0; j < 2; j++) {
        int idx = tid + j * 256;
        int r = idx >> 3, c16 = idx & 7;
        uint32_t sw = swz((uint32_t)(r * 128 + c16 * 16));
        uint4 vh = *(const uint4*)(Vhg + (size_t)r * 512 + c * 64 + c16 * 8);
        uint4 vl = *(const uint4*)(Vlg + (size_t)r * 512 + c * 64 + c16 * 8);
        *(uint4*)(vbase + sw) = vh;
        *(uint4*)(vbase + 8192 + sw) = vl;
    }
}
#endif

__global__ void __launch_bounds__(256, 2) attn_tc_kernel()
{
    extern __shared__ char smem[];
    const int tid = threadIdx.x;
    const int qb = blockIdx.x, e = blockIdx.y, n = blockIdx.z;
    const size_t plane = (size_t)(n * 64 + e);
    const size_t qk_base = plane * 512 * 64;
    const __nv_bfloat16* Qhg = g_Qhi + qk_base + (size_t)qb * 128 * 64;
    const __nv_bfloat16* Qlg = g_Qlo + qk_base + (size_t)qb * 128 * 64;
    const __nv_bfloat16* Khg = g_Khi + qk_base;
    const __nv_bfloat16* Klg = g_Klo + qk_base;
    const __nv_bfloat16* Vhg = g_Vthi + plane * 64 * 512;
    const __nv_bfloat16* Vlg = g_Vtlo + plane * 64 * 512;

#if ATTN_TCGEN
    const uint32_t sb = smem_u32(smem);
    const int wid = tid >> 5, lid = tid & 31;
    const int row = (wid & 3) * 32 + lid;
    const int cb  = (wid >> 2) * 32;

    if (wid == 0) {
        TC_ALLOC(sb + SM_CTRL, 256);
        TC_RELINQ();
    }
    if (tid == 0) {
        MBAR_INIT(sb + SM_CTRL + 8, 1);
        MBAR_INIT(sb + SM_CTRL + 16, 1);
        MBAR_INIT(sb + SM_CTRL + 24, 1);
    }
    __syncthreads();
    uint32_t tmem;
    asm volatile("ld.shared.b32 %0, [%1];" : "=r"(tmem) : "r"(sb + SM_CTRL));
    const uint32_t tQA = tmem;
    uint32_t tS[2]; tS[0] = tmem + 64; tS[1] = tmem + 128;
    uint32_t mbS[2]; mbS[0] = sb + SM_CTRL + 8; mbS[1] = sb + SM_CTRL + 16;
    const uint32_t mb2 = sb + SM_CTRL + 24;
    const uint32_t tO = tmem + 192;

    if (tid < 128) {
        uint32_t qh[32], ql[32];
        const uint4* ph = (const uint4*)(Qhg + (size_t)tid * 64);
        const uint4* pl = (const uint4*)(Qlg + (size_t)tid * 64);
        #pragma unroll
        for (int j = 0; j < 8; j++) {
            uint4 a = ph[j];
            qh[j * 4 + 0] = a.x; qh[j * 4 + 1] = a.y;
            qh[j * 4 + 2] = a.z; qh[j * 4 + 3] = a.w;
            uint4 b = pl[j];
            ql[j * 4 + 0] = b.x; ql[j * 4 + 1] = b.y;
            ql[j * 4 + 2] = b.z; ql[j * 4 + 3] = b.w;
        }
        const uint32_t woff = (uint32_t)(tid >> 5) << 21;
        TC_ST_X32(tQA + woff, qh);
        TC_ST_X32(tQA + 32 + woff, ql);
        TC_WAIT_ST();
    }
    load_k_chunk(smem, Khg, Klg, 0, 0, tid);
    load_v_chunk(smem, Vhg, Vlg, 0, 0, tid);
    FENCE_ASYNC();
    TC_FENCE_BEFORE();
    __syncthreads();

    const uint64_t dPh = make_desc(sb + SM_PHI), dPl = make_desc(sb + SM_PLO);
    uint64_t dKh[2], dKl[2], dVh[2], dVl[2];
    #pragma unroll
    for (int b = 0; b < 2; b++) {
        dKh[b] = make_desc(sb + SM_K + b * 16384);
        dKl[b] = make_desc(sb + SM_K + b * 16384 + 8192);
        dVh[b] = make_desc(sb + SM_V + b * 16384);
        dVl[b] = make_desc(sb + SM_V + b * 16384 + 8192);
    }

    if (wid == 0) {
        TC_FENCE_AFTER();
        if (elect_one()) {
            issue_3pass_ts(tS[0], tQA, dKh[0], dKl[0]);
            TC_COMMIT(mbS[0]);
        }
    }

    float l_part = 0.0f;
    uint32_t sreg[32];

    for (int kc = 0; kc < 8; kc++) {
        if (kc > 0) MBAR_WAIT(mb2, (kc - 1) & 1);
        if (kc < 7) {
            load_k_chunk(smem, Khg, Klg, kc + 1, (kc + 1) & 1, tid);
            load_v_chunk(smem, Vhg, Vlg, kc + 1, (kc + 1) & 1, tid);
            FENCE_ASYNC();
        }
        __syncthreads();
        if (kc < 7 && wid == 0) {
            TC_FENCE_AFTER();
            if (elect_one()) {
                issue_3pass_ts(tS[(kc + 1) & 1], tQA,
                               dKh[(kc + 1) & 1], dKl[(kc + 1) & 1]);
                TC_COMMIT(mbS[(kc + 1) & 1]);
            }
        }

        MBAR_WAIT(mbS[kc & 1], (kc >> 1) & 1);
        TC_FENCE_AFTER();
        TC_LD_X32(sreg, tS[kc & 1] + cb);
        TC_WAIT_LD();

        float l_loc = 0.0f;
        #pragma unroll
        for (int c = 0; c < 32; c++) {
            float sv = __uint_as_float(sreg[c]);
            float pe = __expf(sv * 0.125f);
            sreg[c] = __float_as_uint(pe);
            l_loc += pe;
        }
        l_part += l_loc;

        #pragma unroll
        for (int g = 0; g < 4; g++) {
            uint32_t hw[4], lw[4];
            #pragma unroll
            for (int x = 0; x < 4; x++) {
                float p0 = __uint_as_float(sreg[g * 8 + x * 2]);
                float p1 = __uint_as_float(sreg[g * 8 + x * 2 + 1]);
                uint32_t hi;
                asm("cvt.rn.bf16x2.f32 %0, %1, %2;" : "=r"(hi) : "f"(p1), "f"(p0));
                float hf0 = __uint_as_float(hi << 16);
                float hf1 = __uint_as_float(hi & 0xFFFF0000u);
                uint32_t lo;
                asm("cvt.rn.bf16x2.f32 %0, %1, %2;"
                    : "=r"(lo) : "f"(p1 - hf1), "f"(p0 - hf0));
                hw[x] = hi; lw[x] = lo;
            }
            uint32_t sw = swz((uint32_t)(row * 128 + cb * 2 + g * 16));
            *(uint4*)(smem + SM_PHI + sw) = make_uint4(hw[0], hw[1], hw[2], hw[3]);
            *(uint4*)(smem + SM_PLO + sw) = make_uint4(lw[0], lw[1], lw[2], lw[3]);
        }
        TC_FENCE_BEFORE();
        FENCE_ASYNC();
        __syncthreads();

        if (wid == 0) {
            TC_FENCE_AFTER();
            if (elect_one()) {
                issue_3pass(tO, dPh, dPl, dVh[kc & 1], dVl[kc & 1], kc > 0);
                TC_COMMIT(mb2);
            }
        }
    }

    MBAR_WAIT(mb2, 1);
    TC_FENCE_AFTER();

    *(float*)(smem + SM_RED + tid * 4) = l_part;
    TC_LD_X32(sreg, tO + cb);
    TC_WAIT_LD();
    TC_FENCE_BEFORE();
    __syncthreads();
    const float l_sum = l_part + *(float*)(smem + SM_RED + (tid ^ 128) * 4);

    const float inv = 1.0f / l_sum;
    float* Og = g_Op + plane * 512 * 64 + (size_t)qb * 128 * 64
              + (size_t)row * 64 + cb;
    #pragma unroll
    for (int c4 = 0; c4 < 32; c4 += 4) {
        float4 ov = make_float4(__uint_as_float(sreg[c4 + 0]) * inv,
                                __uint_as_float(sreg[c4 + 1]) * inv,
                                __uint_as_float(sreg[c4 + 2]) * inv,
                                __uint_as_float(sreg[c4 + 3]) * inv);
        *(float4*)(Og + c4) = ov;
    }

    __syncthreads();
    if (wid == 0) TC_DEALLOC(tmem, 256);

#else   // ---------------- scalar fallback (non-'a' target) -----------------
    float* sK = (float*)smem;
    float* sV = sK + 64 * 65;

    float qreg[64];
    if (tid < 128) {
        #pragma unroll
        for (int t = 0; t < 64; t++)
            qreg[t] = __bfloat162float(Qhg[tid * 64 + t]) +
                      __bfloat162float(Qlg[tid * 64 + t]);
    }

    float o[64];
    #pragma unroll
    for (int t = 0; t < 64; t++) o[t] = 0.0f;
    float l_sum = 0.0f;

    for (int kc = 0; kc < 8; kc++) {
        __syncthreads();
        for (int i = tid; i < 4096; i += 256) {
            int r = i >> 6, c = i & 63;
            sK[r * 65 + c] = __bfloat162float(Khg[(size_t)(kc * 64 + r) * 64 + c]) +
                             __bfloat162float(Klg[(size_t)(kc * 64 + r) * 64 + c]);
            sV[r * 65 + c] = __bfloat162float(Vhg[(size_t)c * 512 + kc * 64 + r]) +
                             __bfloat162float(Vlg[(size_t)c * 512 + kc * 64 + r]);
        }
        __syncthreads();

        if (tid < 128) {
            for (int k = 0; k < 64; k++) {
                float s = 0.0f;
                #pragma unroll 16
                for (int t = 0; t < 64; t++) s = fmaf(qreg[t], sK[k * 65 + t], s);
                float p = __expf(s * 0.125f);
                l_sum += p;
                #pragma unroll 16
                for (int t = 0; t < 64; t++) o[t] = fmaf(p, sV[k * 65 + t], o[t]);
            }
        }
    }

    if (tid < 128) {
        const float inv = 1.0f / l_sum;
        float* Og = g_Op + plane * 512 * 64 + (size_t)qb * 128 * 64
                  + (size_t)tid * 64;
        #pragma unroll
        for (int c = 0; c < 64; c++) Og[c] = o[c] * inv;
    }
#endif
}

// ============================================================================
// Kernel 3: tensor-core output projection, 256 threads x 3 CTAs/SM.
// grid (256 qpair, 8 n). Pack phase g-split across thread groups; epilogue
// column-split across warp halves.
// ============================================================================
#define OSTG   0
#define OSTG_PITCH 68
#define OX_HI  17408
#define OX_LO  33792
#define OW_HI  50176
#define OW_LO  58368
#define OB_    66560
#define OCTRL  66816
#define O_TOTAL (OCTRL + 128)

__global__ void __launch_bounds__(256, 3) out_tc_kernel(
    const float* __restrict__ Wo, const float* __restrict__ bo,
    float* __restrict__ out)
{
    extern __shared__ char smem[];
    const int tid = threadIdx.x;
    const int qp = blockIdx.x, n = blockIdx.y;

#if ATTN_TCGEN
    const uint32_t sb = smem_u32(smem);
    const int wid = tid >> 5, lid = tid & 31;

    if (wid == 0) {
        TC_ALLOC(sb + OCTRL, 128);
        TC_RELINQ();
    }
    if (tid == 0) MBAR_INIT(sb + OCTRL + 8, 1);
    if (tid < 64) *(float*)(smem + OB_ + tid * 4) = bo[tid];
    __syncthreads();
    uint32_t tmem;
    asm volatile("ld.shared.b32 %0, [%1];" : "=r"(tmem) : "r"(sb + OCTRL));
    const uint32_t mb = sb + OCTRL + 8;

    load_w_tile(smem, OW_HI, OW_LO, Wo, tid);

    float* stg = (float*)(smem + OSTG);
    #pragma unroll
    for (int qi = 0; qi < 2; qi++) {
        const int q = qp * 2 + qi;
        if (qi == 1) __syncthreads();
        #pragma unroll
        for (int j = 0; j < 4; j++) {
            int u = tid + j * 256;        // 0..1023
            int e = u >> 4, t4 = (u & 15) * 4;
            float4 v = *(const float4*)(g_Op +
                (((size_t)n * 64 + e) * 512 + q) * 64 + t4);
            float* d = &stg[e * OSTG_PITCH + t4];
            d[0] = v.x; d[1] = v.y; d[2] = v.z; d[3] = v.w;
        }
        __syncthreads();
        // transpose-pack: unit = (gpair = tid>>7, eh = (tid>>6)&1, t = tid&63)
        {
            const int t = tid & 63, eh = (tid >> 6) & 1, gp = tid >> 7;
            const int r = qi * 64 + t;
            #pragma unroll
            for (int gg = 0; gg < 2; gg++) {
                const int g = gp * 2 + gg;
                uint32_t hw[4], lw[4];
                #pragma unroll
                for (int x = 0; x < 4; x++) {
                    int e = eh * 32 + g * 8 + x * 2;
                    float v0 = stg[e * OSTG_PITCH + t];
                    float v1 = stg[(e + 1) * OSTG_PITCH + t];
                    uint32_t hi;
                    asm("cvt.rn.bf16x2.f32 %0, %1, %2;"
                        : "=r"(hi) : "f"(v1), "f"(v0));
                    float hf0 = __uint_as_float(hi << 16);
                    float hf1 = __uint_as_float(hi & 0xFFFF0000u);
                    uint32_t lo;
                    asm("cvt.rn.bf16x2.f32 %0, %1, %2;"
                        : "=r"(lo) : "f"(v1 - hf1), "f"(v0 - hf0));
                    hw[x] = hi; lw[x] = lo;
                }
                uint32_t sw = swz((uint32_t)(r * 128 + eh * 64 + g * 16));
                *(uint4*)(smem + OX_HI + sw) = make_uint4(hw[0], hw[1], hw[2], hw[3]);
                *(uint4*)(smem + OX_LO + sw) = make_uint4(lw[0], lw[1], lw[2], lw[3]);
            }
        }
    }
    FENCE_ASYNC();
    TC_FENCE_BEFORE();
    __syncthreads();

    if (wid == 0) {
        TC_FENCE_AFTER();
        if (elect_one()) {
            issue_3pass(tmem, make_desc(sb + OX_HI), make_desc(sb + OX_LO),
                        make_desc(sb + OW_HI), make_desc(sb + OW_LO), false);
            TC_COMMIT(mb);
        }
    }
    MBAR_WAIT(mb, 0);
    TC_FENCE_AFTER();

    // ---- Epilogue (column-split): row = (wid&3)*32+lid, cols (wid>>2)*32 ----
    {
        const int row128 = (wid & 3) * 32 + lid;
        const int cc = (wid >> 2) * 32;
        const int qi = row128 >> 6, t = row128 & 63;
        const int q = qp * 2 + qi;
        float* ob = out + (((size_t)n * 64 + t) * 512 + q) * 64 + cc;
        const float* sbias = (const float*)(smem + OB_) + cc;
        uint32_t sreg[32];
        TC_LD_X32(sreg, tmem + cc);
        TC_WAIT_LD();
        #pragma unroll
        for (int d4 = 0; d4 < 32; d4 += 4) {
            float4 v = make_float4(
                __uint_as_float(sreg[d4 + 0]) + sbias[d4 + 0],
                __uint_as_float(sreg[d4 + 1]) + sbias[d4 + 1],
                __uint_as_float(sreg[d4 + 2]) + sbias[d4 + 2],
                __uint_as_float(sreg[d4 + 3]) + sbias[d4 + 3]);
            *(float4*)(ob + d4) = v;
        }
    }
    TC_FENCE_BEFORE();
    __syncthreads();
    if (wid == 0) TC_DEALLOC(tmem, 128);

#else   // ---------------- scalar fallback (non-'a' target) -----------------
    __shared__ float sWf[64 * 64];
    __shared__ float sbv[64];
    for (int i = tid; i < 4096; i += 256) sWf[i] = Wo[i];
    if (tid < 64) sbv[tid] = bo[tid];
    __syncthreads();
    for (int idx = tid; idx < 128 * 64; idx += 256) {
        int r = idx >> 6, d = idx & 63;
        int qi = r >> 6, t = r & 63;
        int q = qp * 2 + qi;
        float s = 0.0f;
        for (int e = 0; e < 64; e++)
            s = fmaf(g_Op[(((size_t)n * 64 + e) * 512 + q) * 64 + t],
                     sWf[d * 64 + e], s);
        out[(((size_t)n * 64 + t) * 512 + q) * 64 + d] = s + sbv[d];
    }
#endif
}

// ---------------------------------------------------------------------------
extern "C" void kernel_launch(void* const* d_in, const int* in_sizes, int n_in,
                              void* d_out, int out_size)
{
    const float* value = (const float*)d_in[0];
    const float* key   = (const float*)d_in[1];
    const float* query = (const float*)d_in[2];
    const float* Wv    = (const float*)d_in[3];
    const float* Wk    = (const float*)d_in[4];
    const float* Wq    = (const float*)d_in[5];
    const float* Wo    = (const float*)d_in[6];
    const float* bo    = (const float*)d_in[7];
    float* out = (float*)d_out;

    cudaFuncSetAttribute(proj_tc_kernel,
                         cudaFuncAttributeMaxDynamicSharedMemorySize, P_TOTAL);
    cudaFuncSetAttribute(attn_tc_kernel,
                         cudaFuncAttributeMaxDynamicSharedMemorySize, SM_TOTAL);
    cudaFuncSetAttribute(out_tc_kernel,
                         cudaFuncAttributeMaxDynamicSharedMemorySize, O_TOTAL);

    dim3 g1(256, 8, 3);
    proj_tc_kernel<<<g1, 256, P_TOTAL>>>(query, key, value, Wq, Wk, Wv);

    dim3 g2(4, 64, 8);
    attn_tc_kernel<<<g2, 256, SM_TOTAL>>>();

    dim3 g3(256, 8);
    out_tc_kernel<<<g3, 256, O_TOTAL>>>(Wo, bo, out);
}